// round 15
// baseline (speedup 1.0000x reference)
#include <cuda_runtime.h>
#include <cuda_bf16.h>
#include <cuda_fp16.h>

// Problem constants
#define R_DIM 128
#define W_DIM 256
#define DNODE 256
#define DEDGE 128
#define H_N   8
#define DHEAD 32
#define NTOK  (R_DIM * W_DIM)       // 32768
#define NEGMAX (-3.4028234663852886e38f)

// ---------------- scratch (device globals: allocation-free) ----------------
__device__ float g_q   [NTOK * DNODE];          // [rh][i][32] fp32 (unscaled)
__device__ float g_gate[NTOK * DNODE];
__device__ __half g_bias[H_N * W_DIM * W_DIM];  // [h][i][j], fp16 (masked = -65504)
// bf16 split planes (hi + lo ~= fp32)
__device__ __nv_bfloat16 g_xnh [NTOK * DNODE];
__device__ __nv_bfloat16 g_xnl [NTOK * DNODE];
__device__ __nv_bfloat16 g_atth[NTOK * DNODE];
__device__ __nv_bfloat16 g_attl[NTOK * DNODE];
__device__ __nv_bfloat16 g_wph [1024 * 256];    // [n][k]
__device__ __nv_bfloat16 g_wpl [1024 * 256];
__device__ __nv_bfloat16 g_woh [256 * 256];
__device__ __nv_bfloat16 g_wol [256 * 256];
__device__ __nv_bfloat16 g_kh  [NTOK * DNODE];  // [rh][j][32d]
__device__ __nv_bfloat16 g_kl  [NTOK * DNODE];
__device__ __nv_bfloat16 g_vh  [NTOK * DNODE];  // [rh][32d][256j] (transposed)
__device__ __nv_bfloat16 g_vl  [NTOK * DNODE];

// ---------------- helpers ----------------
__device__ __forceinline__ void mma_bf16(float* d,
                                         unsigned a0, unsigned a1, unsigned a2, unsigned a3,
                                         unsigned b0, unsigned b1) {
    asm volatile(
        "mma.sync.aligned.m16n8k16.row.col.f32.bf16.bf16.f32 "
        "{%0,%1,%2,%3}, {%4,%5,%6,%7}, {%8,%9}, {%0,%1,%2,%3};"
        : "+f"(d[0]), "+f"(d[1]), "+f"(d[2]), "+f"(d[3])
        : "r"(a0), "r"(a1), "r"(a2), "r"(a3), "r"(b0), "r"(b1));
}
__device__ __forceinline__ void split_bf16(float x, __nv_bfloat16& hi, __nv_bfloat16& lo) {
    hi = __float2bfloat16(x);
    lo = __float2bfloat16(x - __bfloat162float(hi));
}
__device__ __forceinline__ unsigned bfpack(__nv_bfloat16 a, __nv_bfloat16 b) {
    return (unsigned)__bfloat16_as_ushort(a) | ((unsigned)__bfloat16_as_ushort(b) << 16);
}
__device__ __forceinline__ void split2(float a, float b, unsigned& hi, unsigned& lo) {
    __nv_bfloat16 ha, la, hb, lb;
    split_bf16(a, ha, la);
    split_bf16(b, hb, lb);
    hi = bfpack(ha, hb);
    lo = bfpack(la, lb);
}
#define CP16(dst_u32, src_ptr) \
    asm volatile("cp.async.ca.shared.global [%0], [%1], 16;" :: "r"(dst_u32), "l"(src_ptr))
__device__ __forceinline__ void cp_commit() { asm volatile("cp.async.commit_group;"); }
__device__ __forceinline__ void cp_wait0()  { asm volatile("cp.async.wait_group 0;"); }
__device__ __forceinline__ void cp_wait1()  { asm volatile("cp.async.wait_group 1;"); }
#define LDSM4(r0, r1, r2, r3, addr) \
    asm volatile("ldmatrix.sync.aligned.m8n8.x4.shared.b16 {%0,%1,%2,%3}, [%4];" \
        : "=r"(r0), "=r"(r1), "=r"(r2), "=r"(r3) : "r"(addr));

// GEMM smem: RS=16 (no pad), XOR swizzle (chunk ^= (row&4)<<1)
#define RS 16
#define PLANE (128 * RS)

// ---------------- kernel 1 (fused): LN(x) + weight split ----------
#define PREP_LN_BLKS   (NTOK / 8)            // 4096
#define PREP_W_BLKS    1280
__global__ void prep_kernel(const float* __restrict__ x,
                            const float* __restrict__ g,
                            const float* __restrict__ b,
                            const float* __restrict__ Wq, const float* __restrict__ Wkv,
                            const float* __restrict__ Wg, const float* __restrict__ Wo) {
    int bid = blockIdx.x;
    if (bid < PREP_LN_BLKS) {
        // ---- LayerNorm(x) ----
        int warp = threadIdx.x >> 5, lane = threadIdx.x & 31;
        int tok  = bid * 8 + warp;
        const float* xp = x + (size_t)tok * 256 + lane * 8;
        float4 a0 = *(const float4*)xp;
        float4 a1 = *(const float4*)(xp + 4);
        float s  = a0.x + a0.y + a0.z + a0.w + a1.x + a1.y + a1.z + a1.w;
        float ss = a0.x*a0.x + a0.y*a0.y + a0.z*a0.z + a0.w*a0.w
                 + a1.x*a1.x + a1.y*a1.y + a1.z*a1.z + a1.w*a1.w;
        #pragma unroll
        for (int off = 16; off; off >>= 1) {
            s  += __shfl_xor_sync(0xffffffffu, s,  off);
            ss += __shfl_xor_sync(0xffffffffu, ss, off);
        }
        float mu  = s * (1.0f / 256.0f);
        float var = ss * (1.0f / 256.0f) - mu * mu;
        float rs  = rsqrtf(var + 1e-5f);
        float4 g0 = *(const float4*)(g + lane * 8);
        float4 g1 = *(const float4*)(g + lane * 8 + 4);
        float4 b0 = *(const float4*)(b + lane * 8);
        float4 b1 = *(const float4*)(b + lane * 8 + 4);
        float v[8];
        v[0] = (a0.x - mu) * rs * g0.x + b0.x;
        v[1] = (a0.y - mu) * rs * g0.y + b0.y;
        v[2] = (a0.z - mu) * rs * g0.z + b0.z;
        v[3] = (a0.w - mu) * rs * g0.w + b0.w;
        v[4] = (a1.x - mu) * rs * g1.x + b1.x;
        v[5] = (a1.y - mu) * rs * g1.y + b1.y;
        v[6] = (a1.z - mu) * rs * g1.z + b1.z;
        v[7] = (a1.w - mu) * rs * g1.w + b1.w;
        unsigned hu[4], lu[4];
        #pragma unroll
        for (int p = 0; p < 4; p++) split2(v[2 * p], v[2 * p + 1], hu[p], lu[p]);
        size_t off = (size_t)tok * 256 + lane * 8;
        *(uint4*)&g_xnh[off] = make_uint4(hu[0], hu[1], hu[2], hu[3]);
        *(uint4*)&g_xnl[off] = make_uint4(lu[0], lu[1], lu[2], lu[3]);
    } else {
        // ---- weight split ----
        int n = bid - PREP_LN_BLKS, k = threadIdx.x;
        float w;
        if (n < 256)       w = Wq [(size_t)k * 256 + n];
        else if (n < 768)  w = Wkv[(size_t)k * 512 + (n - 256)];
        else if (n < 1024) w = Wg [(size_t)k * 256 + (n - 768)];
        else               w = Wo [(size_t)k * 256 + (n - 1024)];
        __nv_bfloat16 h, l;
        split_bf16(w, h, l);
        if (n < 1024) {
            g_wph[(size_t)n * 256 + k] = h;
            g_wpl[(size_t)n * 256 + k] = l;
        } else {
            g_woh[(size_t)(n - 1024) * 256 + k] = h;
            g_wol[(size_t)(n - 1024) * 256 + k] = l;
        }
    }
}

// ---------------- bf16x3 GEMM (ldmatrix + swizzle + 3-stage pipeline) ----------------
#define GEMM_SMEM()                                                            \
    __shared__ __nv_bfloat16 sAh[3][PLANE], sAl[3][PLANE];                     \
    __shared__ __nv_bfloat16 sBh[3][PLANE], sBl[3][PLANE];

#define GEMM_ISSUE(buf, kt, Ahp, Alp, Bhp, Blp, abase, nbase)                  \
    {                                                                          \
        int k0 = (kt) * 16 + ch;                                               \
        unsigned doff = ((unsigned)(buf) * PLANE + row * RS + chsw) * 2;       \
        CP16(sAh_u + doff, (Ahp) + (size_t)((abase) + row) * 256 + k0);        \
        CP16(sAl_u + doff, (Alp) + (size_t)((abase) + row) * 256 + k0);        \
        CP16(sBh_u + doff, (Bhp) + (size_t)((nbase) + row) * 256 + k0);        \
        CP16(sBl_u + doff, (Blp) + (size_t)((nbase) + row) * 256 + k0);        \
        cp_commit();                                                           \
    }

#define GEMM_LANEOFF()                                                         \
    int arow  = (lane & 7) + ((lane >> 3) & 1) * 8;                            \
    int achnk = ((lane >> 4) * 8) ^ ((arow & 4) << 1);                         \
    int brow  = (lane & 7) + ((lane >> 4) & 1) * 8;                            \
    int bchnk = (((lane >> 3) & 1) * 8) ^ ((brow & 4) << 1);

#define GEMM_KTILE(st)                                                         \
    {                                                                          \
        unsigned stoff = (unsigned)(st) * PLANE * 2;                           \
        unsigned bh[4][2], bl[4][2];                                           \
        _Pragma("unroll")                                                      \
        for (int p = 0; p < 2; p++) {                                          \
            unsigned bo = ((wn * 32 + p * 16 + brow) * RS + bchnk) * 2;        \
            LDSM4(bh[2*p][0], bh[2*p][1], bh[2*p+1][0], bh[2*p+1][1],          \
                  sBh_u + stoff + bo)                                          \
            LDSM4(bl[2*p][0], bl[2*p][1], bl[2*p+1][0], bl[2*p+1][1],          \
                  sBl_u + stoff + bo)                                          \
        }                                                                      \
        _Pragma("unroll")                                                      \
        for (int am = 0; am < 4; am++) {                                       \
            unsigned ao = ((wm * 64 + am * 16 + arow) * RS + achnk) * 2;       \
            unsigned ah0, ah1, ah2, ah3, al0, al1, al2, al3;                   \
            LDSM4(ah0, ah1, ah2, ah3, sAh_u + stoff + ao)                      \
            LDSM4(al0, al1, al2, al3, sAl_u + stoff + ao)                      \
            _Pragma("unroll")                                                  \
            for (int an = 0; an < 4; an++) {                                   \
                float* ac = acc[am][an];                                       \
                mma_bf16(ac, ah0, ah1, ah2, ah3, bh[an][0], bh[an][1]);        \
                mma_bf16(ac, ah0, ah1, ah2, ah3, bl[an][0], bl[an][1]);        \
                mma_bf16(ac, al0, al1, al2, al3, bh[an][0], bh[an][1]);        \
            }                                                                  \
        }                                                                      \
    }

#define GEMM_MAINLOOP(Ahp, Alp, Bhp, Blp, abase, nbase)                        \
    GEMM_ISSUE(0, 0, Ahp, Alp, Bhp, Blp, abase, nbase)                         \
    GEMM_ISSUE(1, 1, Ahp, Alp, Bhp, Blp, abase, nbase)                         \
    for (int kt = 0; kt < 16; kt++) {                                          \
        if (kt < 15) cp_wait1(); else cp_wait0();                              \
        __syncthreads();                                                       \
        if (kt <= 13) {                                                        \
            int nbuf = (kt + 2) % 3;                                           \
            GEMM_ISSUE(nbuf, kt + 2, Ahp, Alp, Bhp, Blp, abase, nbase)         \
        }                                                                      \
        GEMM_KTILE(kt % 3)                                                     \
    }

// ---------------- kernel 3: projection GEMM (bf16x3) + co-scheduled bias blocks ----
// 1D grid of 10240 blocks: bid%5==0 -> proj block (2048), else bias block (8192)
__global__ void __launch_bounds__(256, 2)
proj_mma(const float* __restrict__ bg,
         const float* __restrict__ edges,
         const float* __restrict__ lg,
         const float* __restrict__ lb,
         const float* __restrict__ We,
         const unsigned int* __restrict__ emask) {
    GEMM_SMEM()
    int bid = blockIdx.x;
    int grp = bid / 5, pos = bid % 5;
    int t = threadIdx.x, lane = t & 31, warp = t >> 5;

    if (pos != 0) {
        // ---------- bias block: edge LN + W_edge + edge_mask -> fp16 [h][i][j] ------
        float* sW = (float*)&sAh[0][0];          // 1024 floats
        float* sg2 = sW + DEDGE * H_N;           // 128
        float* sb2 = sg2 + DEDGE;                // 128
        for (int l = t; l < DEDGE * H_N; l += 256) sW[l] = We[l];
        if (t < DEDGE) { sg2[t] = lg[t]; sb2[t] = lb[t]; }
        __syncthreads();

        int bbid = grp * 4 + (pos - 1);          // 0..8191
        int p = bbid * 8 + warp;
        int i = p >> 8, j = p & 255;

        if (emask[p] == 0u) {
            if (lane < 8)
                g_bias[((size_t)(lane * 256 + i)) * 256 + j] = __float2half(-65504.0f);
            return;
        }
        const float* ep = edges + (size_t)p * DEDGE + lane * 4;
        float4 e = *(const float4*)ep;
        float s  = e.x + e.y + e.z + e.w;
        float ss = e.x*e.x + e.y*e.y + e.z*e.z + e.w*e.w;
        #pragma unroll
        for (int off = 16; off; off >>= 1) {
            s  += __shfl_xor_sync(0xffffffffu, s,  off);
            ss += __shfl_xor_sync(0xffffffffu, ss, off);
        }
        float mu  = s * (1.0f / 128.0f);
        float var = ss * (1.0f / 128.0f) - mu * mu;
        float rs  = rsqrtf(var + 1e-5f);
        int e0 = lane * 4;
        float en[4];
        en[0] = (e.x - mu) * rs * sg2[e0 + 0] + sb2[e0 + 0];
        en[1] = (e.y - mu) * rs * sg2[e0 + 1] + sb2[e0 + 1];
        en[2] = (e.z - mu) * rs * sg2[e0 + 2] + sb2[e0 + 2];
        en[3] = (e.w - mu) * rs * sg2[e0 + 3] + sb2[e0 + 3];
        float acc[8];
        #pragma unroll
        for (int h = 0; h < 8; h++) acc[h] = 0.0f;
        #pragma unroll
        for (int c2 = 0; c2 < 4; c2++) {
            const float* wr = &sW[(e0 + c2) * 8];
            #pragma unroll
            for (int h = 0; h < 8; h++) acc[h] += en[c2] * wr[h];
        }
        #pragma unroll
        for (int h = 0; h < 8; h++) {
            #pragma unroll
            for (int off = 16; off; off >>= 1)
                acc[h] += __shfl_xor_sync(0xffffffffu, acc[h], off);
        }
        if (lane == 0) {
            #pragma unroll
            for (int h = 0; h < 8; h++)
                g_bias[((size_t)(h * 256 + i)) * 256 + j] = __float2half(acc[h]);
        }
        return;
    }

    // ---------- proj block ----------
    int bn = grp & 7, bm = grp >> 3;
    int wm = warp >> 2, wn = warp & 3;
    int g = lane >> 2, c = lane & 3;
    int nb = bn * 128;
    int abase = bm * 128;

    unsigned sAh_u = (unsigned)__cvta_generic_to_shared(sAh);
    unsigned sAl_u = (unsigned)__cvta_generic_to_shared(sAl);
    unsigned sBh_u = (unsigned)__cvta_generic_to_shared(sBh);
    unsigned sBl_u = (unsigned)__cvta_generic_to_shared(sBl);
    int row = t >> 1, ch = (t & 1) * 8;
    int chsw = ch ^ ((row & 4) << 1);
    GEMM_LANEOFF()

    float acc[4][4][4];
    #pragma unroll
    for (int am = 0; am < 4; am++)
        #pragma unroll
        for (int an = 0; an < 4; an++)
            #pragma unroll
            for (int v = 0; v < 4; v++) acc[am][an][v] = 0.0f;

    GEMM_MAINLOOP(g_xnh, g_xnl, g_wph, g_wpl, abase, nb)

    #pragma unroll
    for (int am = 0; am < 4; am++) {
        int tok = abase + wm * 64 + am * 16 + g;
        int rr = tok >> 8, iw = tok & 255;
        #pragma unroll
        for (int an = 0; an < 4; an++) {
            int gc = nb + wn * 32 + an * 8 + 2 * c;
            float a0 = acc[am][an][0], a1 = acc[am][an][1];
            float a2 = acc[am][an][2], a3 = acc[am][an][3];
            if (gc < 256) {                       // q: fp32, [rh][i][d]
                int hh = gc >> 5, d8 = gc & 31;
                float* p0 = g_q + ((size_t)((rr * 8 + hh) * 256 + iw)) * 32 + d8;
                *(float2*)p0            = make_float2(a0, a1);
                *(float2*)(p0 + 8 * 32) = make_float2(a2, a3);
            } else if (gc < 512) {                // k: bf16 split, [rh][j][d]
                int cq = gc - 256;
                int hh = cq >> 5, d8 = cq & 31;
                size_t b0 = ((size_t)((rr * 8 + hh) * 256 + iw)) * 32 + d8;
                unsigned hi0, lo0, hi1, lo1;
                split2(a0, a1, hi0, lo0);
                split2(a2, a3, hi1, lo1);
                *(unsigned*)&g_kh[b0] = hi0;  *(unsigned*)&g_kl[b0] = lo0;
                *(unsigned*)&g_kh[b0 + 256] = hi1;  *(unsigned*)&g_kl[b0 + 256] = lo1;
            } else if (gc < 768) {                // v: bf16 split, transposed [rh][d][j]
                int cq = gc - 512;
                int hh = cq >> 5, d8 = cq & 31;
                size_t vb = ((size_t)((rr * 8 + hh) * 32 + d8)) * 256 + iw;
                __nv_bfloat16 h0, l0, h1, l1;
                split_bf16(a0, h0, l0);  g_vh[vb] = h0;        g_vl[vb] = l0;
                split_bf16(a1, h1, l1);  g_vh[vb + 256] = h1;  g_vl[vb + 256] = l1;
                split_bf16(a2, h0, l0);  g_vh[vb + 8] = h0;    g_vl[vb + 8] = l0;
                split_bf16(a3, h1, l1);  g_vh[vb + 264] = h1;  g_vl[vb + 264] = l1;
            } else {                              // gate: sigmoid fp32
                int gcol = gc - 768;
                float2 bg2 = *(const float2*)(bg + gcol);
                float* p0 = g_gate + (size_t)tok * 256 + gcol;
                float* p1 = p0 + 8 * 256;
                *(float2*)p0 = make_float2(1.0f / (1.0f + __expf(-(a0 + bg2.x))),
                                           1.0f / (1.0f + __expf(-(a1 + bg2.y))));
                *(float2*)p1 = make_float2(1.0f / (1.0f + __expf(-(a2 + bg2.x))),
                                           1.0f / (1.0f + __expf(-(a3 + bg2.y))));
            }
        }
    }
}

// ---------------- kernel 5: output projection (bf16x3) ----------------
__global__ void __launch_bounds__(256, 2)
out_mma(const float* __restrict__ bo, float* __restrict__ out) {
    GEMM_SMEM()
    int t = threadIdx.x, lane = t & 31, warp = t >> 5;
    int wm = warp >> 2, wn = warp & 3;
    int g = lane >> 2, c = lane & 3;
    int bn = blockIdx.x, bm = blockIdx.y;
    int nb = bn * 128;
    int abase = bm * 128;

    unsigned sAh_u = (unsigned)__cvta_generic_to_shared(sAh);
    unsigned sAl_u = (unsigned)__cvta_generic_to_shared(sAl);
    unsigned sBh_u = (unsigned)__cvta_generic_to_shared(sBh);
    unsigned sBl_u = (unsigned)__cvta_generic_to_shared(sBl);
    int row = t >> 1, ch = (t & 1) * 8;
    int chsw = ch ^ ((row & 4) << 1);
    GEMM_LANEOFF()

    float acc[4][4][4];
    #pragma unroll
    for (int am = 0; am < 4; am++)
        #pragma unroll
        for (int an = 0; an < 4; an++)
            #pragma unroll
            for (int v = 0; v < 4; v++) acc[am][an][v] = 0.0f;

    GEMM_MAINLOOP(g_atth, g_attl, g_woh, g_wol, abase, nb)

    #pragma unroll
    for (int am = 0; am < 4; am++) {
        int tok = abase + wm * 64 + am * 16 + g;
        #pragma unroll
        for (int an = 0; an < 4; an++) {
            int gc = nb + wn * 32 + an * 8 + 2 * c;
            float2 bo2 = *(const float2*)(bo + gc);
            float* p0 = out + (size_t)tok * 256 + gc;
            float* p1 = p0 + 8 * 256;
            *(float2*)p0 = make_float2(acc[am][an][0] + bo2.x, acc[am][an][1] + bo2.y);
            *(float2*)p1 = make_float2(acc[am][an][2] + bo2.x, acc[am][an][3] + bo2.y);
        }
    }
}

// ---------------- kernel 4: attention via bf16x3 mma.sync (16 warps, 16 q/warp) ----
#define A_K_OFF   0
#define A_KL_OFF  2560                // 32 rows * 80 B per plane
#define A_VH_OFF  5120
#define A_VL_OFF  7680
#define A_STAGE   10240
#define A_SMEM    (3 * A_STAGE)       // 30720

__global__ void __launch_bounds__(512, 1)
attn_mma(const unsigned int* __restrict__ mask) {
    extern __shared__ char asmem[];
    __shared__ unsigned mwords[8];

    int t = threadIdx.x, lane = t & 31, w = t >> 5;   // w = 0..15
    int g = lane >> 2, c = lane & 3;
    int rh = blockIdx.x;
    int r = rh >> 3, h = rh & 7;
    unsigned smem_u = (unsigned)__cvta_generic_to_shared(asmem);

    // key-mask ballot words
    if (w == 0) {
        #pragma unroll
        for (int q = 0; q < 8; q++) {
            unsigned bit = (mask[r * 256 + q * 32 + lane] != 0u) ? 1u : 0u;
            unsigned word = __ballot_sync(0xffffffffu, bit);
            if (lane == 0) mwords[q] = word;
        }
    }

    const float sc = 0.17677669529663689f;   // 32^-0.5
    int i0 = w * 16 + g, i1 = i0 + 8;
    int rowv0 = (mask[r * 256 + i0] != 0u);
    int rowv1 = (mask[r * 256 + i1] != 0u);

    // Q fragments (scaled, split)
    unsigned qh[2][4], ql[2][4];
    {
        const float* q0 = g_q + ((size_t)rh * 256 + i0) * 32;
        const float* q1 = g_q + ((size_t)rh * 256 + i1) * 32;
        #pragma unroll
        for (int ks = 0; ks < 2; ks++) {
            float2 x0 = *(const float2*)(q0 + ks * 16 + 2 * c);
            float2 x1 = *(const float2*)(q1 + ks * 16 + 2 * c);
            float2 x2 = *(const float2*)(q0 + ks * 16 + 2 * c + 8);
            float2 x3 = *(const float2*)(q1 + ks * 16 + 2 * c + 8);
            split2(x0.x * sc, x0.y * sc, qh[ks][0], ql[ks][0]);
            split2(x1.x * sc, x1.y * sc, qh[ks][1], ql[ks][1]);
            split2(x2.x * sc, x2.y * sc, qh[ks][2], ql[ks][2]);
            split2(x3.x * sc, x3.y * sc, qh[ks][3], ql[ks][3]);
        }
    }

    float O[4][4];
    float l0 = 0.0f, l1 = 0.0f;
    #pragma unroll
    for (int dt = 0; dt < 4; dt++)
        #pragma unroll
        for (int v = 0; v < 4; v++) O[dt][v] = 0.0f;

    // bias row pointers ([h][i][j] layout, half2 at even j)
    const __half2* bR0 = (const __half2*)&g_bias[((size_t)(h * 256 + i0)) * 256 + 2 * c];
    const __half2* bR1 = (const __half2*)&g_bias[((size_t)(h * 256 + i1)) * 256 + 2 * c];

    const __nv_bfloat16* khb = g_kh + (size_t)rh * 256 * 32;
    const __nv_bfloat16* klb = g_kl + (size_t)rh * 256 * 32;
    const __nv_bfloat16* vhb = g_vh + (size_t)rh * 32 * 256;
    const __nv_bfloat16* vlb = g_vl + (size_t)rh * 32 * 256;

    // per-chunk cp.async (512 threads): exactly 1 KV 16B chunk per thread
    int kvp  = t >> 7;                 // plane 0..3
    int kvr  = (t >> 2) & 31;          // row 0..31
    int kvs  = t & 3;                  // 16B chunk within 64B row

    #define AISSUE(chv)                                                            \
    {                                                                              \
        unsigned sb = smem_u + (unsigned)((chv) % 3) * A_STAGE;                    \
        unsigned kvo = sb + (unsigned)kvp * 2560 + kvr * 80 + kvs * 16;            \
        if (kvp == 0)                                                              \
            CP16(kvo, khb + (size_t)((chv) * 32 + kvr) * 32 + kvs * 8);            \
        else if (kvp == 1)                                                         \
            CP16(kvo, klb + (size_t)((chv) * 32 + kvr) * 32 + kvs * 8);            \
        else if (kvp == 2)                                                         \
            CP16(kvo, vhb + (size_t)kvr * 256 + (chv) * 32 + kvs * 8);             \
        else                                                                       \
            CP16(kvo, vlb + (size_t)kvr * 256 + (chv) * 32 + kvs * 8);             \
        cp_commit();                                                               \
    }

    AISSUE(0)
    AISSUE(1)

    // prefetch bias registers for chunk 0
    __half2 bv0[4], bv1[4];
    #pragma unroll
    for (int jt = 0; jt < 4; jt++) {
        bv0[jt] = bR0[jt * 4];
        bv1[jt] = bR1[jt * 4];
    }

    int brow = (lane & 7) + ((lane >> 4) & 1) * 8;
    int bch  = ((lane >> 3) & 1) * 8;

    for (int chk = 0; chk < 8; chk++) {
        if (chk < 7) cp_wait1(); else cp_wait0();
        __syncthreads();
        if (chk + 2 < 8) AISSUE(chk + 2)

        // consume prefetched bias; immediately prefetch next chunk's bias
        __half2 cb0[4], cb1[4];
        #pragma unroll
        for (int jt = 0; jt < 4; jt++) { cb0[jt] = bv0[jt]; cb1[jt] = bv1[jt]; }
        if (chk < 7) {
            #pragma unroll
            for (int jt = 0; jt < 4; jt++) {
                bv0[jt] = bR0[(chk + 1) * 16 + jt * 4];
                bv1[jt] = bR1[(chk + 1) * 16 + jt * 4];
            }
        }

        int st = chk % 3;
        unsigned sb = smem_u + (unsigned)st * A_STAGE;

        // K fragments
        unsigned kfh[2][4][2], kfl[2][4][2];
        #pragma unroll
        for (int p = 0; p < 2; p++) {
            #pragma unroll
            for (int ks = 0; ks < 2; ks++) {
                unsigned ao = sb + A_K_OFF + (p * 16 + brow) * 80 + (ks * 16 + bch) * 2;
                LDSM4(kfh[ks][2*p][0], kfh[ks][2*p][1], kfh[ks][2*p+1][0], kfh[ks][2*p+1][1], ao)
                unsigned al_ = sb + A_KL_OFF + (p * 16 + brow) * 80 + (ks * 16 + bch) * 2;
                LDSM4(kfl[ks][2*p][0], kfl[ks][2*p][1], kfl[ks][2*p+1][0], kfl[ks][2*p+1][1], al_)
            }
        }

        // S = (q*sc) @ K^T  (bf16x3)
        float S[4][4];
        #pragma unroll
        for (int jt = 0; jt < 4; jt++) {
            #pragma unroll
            for (int v = 0; v < 4; v++) S[jt][v] = 0.0f;
            #pragma unroll
            for (int ks = 0; ks < 2; ks++) {
                mma_bf16(S[jt], qh[ks][0], qh[ks][1], qh[ks][2], qh[ks][3],
                         kfh[ks][jt][0], kfh[ks][jt][1]);
                mma_bf16(S[jt], qh[ks][0], qh[ks][1], qh[ks][2], qh[ks][3],
                         kfl[ks][jt][0], kfl[ks][jt][1]);
                mma_bf16(S[jt], ql[ks][0], ql[ks][1], ql[ks][2], ql[ks][3],
                         kfh[ks][jt][0], kfh[ks][jt][1]);
            }
        }

        // bias + mask + exp
        unsigned mb = mwords[chk];
        #pragma unroll
        for (int jt = 0; jt < 4; jt++) {
            int j0 = jt * 8 + 2 * c;
            float2 f0 = __half22float2(cb0[jt]);
            float2 f1 = __half22float2(cb1[jt]);
            unsigned jm0 = (mb >> j0) & 1u, jm1 = (mb >> (j0 + 1)) & 1u;
            float p00 = jm0 ? __expf(S[jt][0] + f0.x) : 0.0f;
            float p01 = jm1 ? __expf(S[jt][1] + f0.y) : 0.0f;
            float p10 = jm0 ? __expf(S[jt][2] + f1.x) : 0.0f;
            float p11 = jm1 ? __expf(S[jt][3] + f1.y) : 0.0f;
            if (!rowv0) { p00 = 1.0f; p01 = 1.0f; }
            if (!rowv1) { p10 = 1.0f; p11 = 1.0f; }
            l0 += p00 + p01;
            l1 += p10 + p11;
            S[jt][0] = p00; S[jt][1] = p01;
            S[jt][2] = p10; S[jt][3] = p11;
        }

        // O += P @ V  (P split exactly; V split)
        #pragma unroll
        for (int ks = 0; ks < 2; ks++) {
            unsigned vfh[4][2], vfl[4][2];
            #pragma unroll
            for (int p = 0; p < 2; p++) {
                unsigned ao = sb + A_VH_OFF + (p * 16 + brow) * 80 + (ks * 16 + bch) * 2;
                LDSM4(vfh[2*p][0], vfh[2*p][1], vfh[2*p+1][0], vfh[2*p+1][1], ao)
                unsigned al_ = sb + A_VL_OFF + (p * 16 + brow) * 80 + (ks * 16 + bch) * 2;
                LDSM4(vfl[2*p][0], vfl[2*p][1], vfl[2*p+1][0], vfl[2*p+1][1], al_)
            }
            const float* PA = S[2 * ks];
            const float* PB = S[2 * ks + 1];
            unsigned ah0, ah1, ah2, ah3, al0, al1, al2, al3;
            split2(PA[0], PA[1], ah0, al0);
            split2(PA[2], PA[3], ah1, al1);
            split2(PB[0], PB[1], ah2, al2);
            split2(PB[2], PB[3], ah3, al3);
            #pragma unroll
            for (int dt = 0; dt < 4; dt++) {
                mma_bf16(O[dt], ah0, ah1, ah2, ah3, vfh[dt][0], vfh[dt][1]);
                mma_bf16(O[dt], ah0, ah1, ah2, ah3, vfl[dt][0], vfl[dt][1]);
                mma_bf16(O[dt], al0, al1, al2, al3, vfh[dt][0], vfh[dt][1]);
            }
        }
    }
    #undef AISSUE

    // finalize: reduce l over quad, normalize, gate, split-store
    l0 += __shfl_xor_sync(0xffffffffu, l0, 1);
    l0 += __shfl_xor_sync(0xffffffffu, l0, 2);
    l1 += __shfl_xor_sync(0xffffffffu, l1, 1);
    l1 += __shfl_xor_sync(0xffffffffu, l1, 2);
    float inv0 = 1.0f / l0;
    float inv1 = 1.0f / l1;

    int tok0 = r * 256 + i0;
    int tok1 = r * 256 + i1;
    #pragma unroll
    for (int dt = 0; dt < 4; dt++) {
        int col = h * 32 + dt * 8 + 2 * c;
        float2 g0 = *(const float2*)&g_gate[(size_t)tok0 * 256 + col];
        float2 g1 = *(const float2*)&g_gate[(size_t)tok1 * 256 + col];
        float o00 = O[dt][0] * inv0 * g0.x;
        float o01 = O[dt][1] * inv0 * g0.y;
        float o10 = O[dt][2] * inv1 * g1.x;
        float o11 = O[dt][3] * inv1 * g1.y;
        unsigned hi0, lo0, hi1, lo1;
        split2(o00, o01, hi0, lo0);
        split2(o10, o11, hi1, lo1);
        *(unsigned*)&g_atth[(size_t)tok0 * 256 + col] = hi0;
        *(unsigned*)&g_attl[(size_t)tok0 * 256 + col] = lo0;
        *(unsigned*)&g_atth[(size_t)tok1 * 256 + col] = hi1;
        *(unsigned*)&g_attl[(size_t)tok1 * 256 + col] = lo1;
    }
}

// ---------------- launch ----------------
extern "C" void kernel_launch(void* const* d_in, const int* in_sizes, int n_in,
                              void* d_out, int out_size) {
    const float* x      = (const float*)d_in[0];
    const float* edges  = (const float*)d_in[1];
    const unsigned int* mask      = (const unsigned int*)d_in[2];
    const unsigned int* edge_mask = (const unsigned int*)d_in[3];
    const float* ln_g   = (const float*)d_in[4];
    const float* ln_b   = (const float*)d_in[5];
    const float* lne_g  = (const float*)d_in[6];
    const float* lne_b  = (const float*)d_in[7];
    const float* W_edge = (const float*)d_in[8];
    const float* Wq     = (const float*)d_in[9];
    const float* Wkv    = (const float*)d_in[10];
    const float* Wg     = (const float*)d_in[11];
    const float* bg     = (const float*)d_in[12];
    const float* Wo     = (const float*)d_in[13];
    const float* bo     = (const float*)d_in[14];
    float* out = (float*)d_out;

    cudaFuncSetAttribute(attn_mma, cudaFuncAttributeMaxDynamicSharedMemorySize, A_SMEM);

    prep_kernel<<<PREP_LN_BLKS + PREP_W_BLKS, 256>>>(x, ln_g, ln_b, Wq, Wkv, Wg, Wo);
    proj_mma<<<10240, 256>>>(bg, edges, lne_g, lne_b, W_edge, edge_mask);
    attn_mma<<<R_DIM * H_N, 512, A_SMEM>>>(mask);
    out_mma<<<dim3(2, NTOK / 128), 256>>>(bo, out);
}

// round 16
// speedup vs baseline: 1.0731x; 1.0731x over previous
#include <cuda_runtime.h>
#include <cuda_bf16.h>
#include <cuda_fp16.h>

// Problem constants
#define R_DIM 128
#define W_DIM 256
#define DNODE 256
#define DEDGE 128
#define H_N   8
#define DHEAD 32
#define NTOK  (R_DIM * W_DIM)       // 32768
#define NEGMAX (-3.4028234663852886e38f)

// ---------------- scratch (device globals: allocation-free) ----------------
__device__ float g_q   [NTOK * DNODE];          // [rh][i][32] fp32 (unscaled)
__device__ float g_gate[NTOK * DNODE];
__device__ __half g_bias[H_N * W_DIM * W_DIM];  // [h][i][j], fp16 (masked = -65504)
// bf16 split planes (hi + lo ~= fp32)
__device__ __nv_bfloat16 g_xnh [NTOK * DNODE];
__device__ __nv_bfloat16 g_xnl [NTOK * DNODE];
__device__ __nv_bfloat16 g_atth[NTOK * DNODE];
__device__ __nv_bfloat16 g_attl[NTOK * DNODE];
__device__ __nv_bfloat16 g_wph [1024 * 256];    // [n][k]
__device__ __nv_bfloat16 g_wpl [1024 * 256];
__device__ __nv_bfloat16 g_woh [256 * 256];
__device__ __nv_bfloat16 g_wol [256 * 256];
__device__ __nv_bfloat16 g_kh  [NTOK * DNODE];  // [rh][j][32d]
__device__ __nv_bfloat16 g_kl  [NTOK * DNODE];
__device__ __nv_bfloat16 g_vh  [NTOK * DNODE];  // [rh][32d][256j] (transposed)
__device__ __nv_bfloat16 g_vl  [NTOK * DNODE];

// ---------------- helpers ----------------
__device__ __forceinline__ void mma_bf16(float* d,
                                         unsigned a0, unsigned a1, unsigned a2, unsigned a3,
                                         unsigned b0, unsigned b1) {
    asm volatile(
        "mma.sync.aligned.m16n8k16.row.col.f32.bf16.bf16.f32 "
        "{%0,%1,%2,%3}, {%4,%5,%6,%7}, {%8,%9}, {%0,%1,%2,%3};"
        : "+f"(d[0]), "+f"(d[1]), "+f"(d[2]), "+f"(d[3])
        : "r"(a0), "r"(a1), "r"(a2), "r"(a3), "r"(b0), "r"(b1));
}
__device__ __forceinline__ void split_bf16(float x, __nv_bfloat16& hi, __nv_bfloat16& lo) {
    hi = __float2bfloat16(x);
    lo = __float2bfloat16(x - __bfloat162float(hi));
}
__device__ __forceinline__ unsigned bfpack(__nv_bfloat16 a, __nv_bfloat16 b) {
    return (unsigned)__bfloat16_as_ushort(a) | ((unsigned)__bfloat16_as_ushort(b) << 16);
}
__device__ __forceinline__ void split2(float a, float b, unsigned& hi, unsigned& lo) {
    __nv_bfloat16 ha, la, hb, lb;
    split_bf16(a, ha, la);
    split_bf16(b, hb, lb);
    hi = bfpack(ha, hb);
    lo = bfpack(la, lb);
}
#define CP16(dst_u32, src_ptr) \
    asm volatile("cp.async.ca.shared.global [%0], [%1], 16;" :: "r"(dst_u32), "l"(src_ptr))
__device__ __forceinline__ void cp_commit() { asm volatile("cp.async.commit_group;"); }
__device__ __forceinline__ void cp_wait0()  { asm volatile("cp.async.wait_group 0;"); }
__device__ __forceinline__ void cp_wait1()  { asm volatile("cp.async.wait_group 1;"); }
#define LDSM4(r0, r1, r2, r3, addr) \
    asm volatile("ldmatrix.sync.aligned.m8n8.x4.shared.b16 {%0,%1,%2,%3}, [%4];" \
        : "=r"(r0), "=r"(r1), "=r"(r2), "=r"(r3) : "r"(addr));

// GEMM smem: RS=16 (no pad), XOR swizzle (chunk ^= (row&4)<<1)
#define RS 16
#define PLANE (128 * RS)

// ---------------- kernel 1 (fused): LN(x) + weight split + edge bias ----------
#define PREP_LN_BLKS   (NTOK / 8)            // 4096
#define PREP_W_BLKS    1280
#define PREP_BIAS_BLKS ((W_DIM * W_DIM) / 8) // 8192
__global__ void prep_kernel(const float* __restrict__ x,
                            const float* __restrict__ g,
                            const float* __restrict__ b,
                            const float* __restrict__ Wq, const float* __restrict__ Wkv,
                            const float* __restrict__ Wg, const float* __restrict__ Wo,
                            const float* __restrict__ edges,
                            const float* __restrict__ lg,
                            const float* __restrict__ lb,
                            const float* __restrict__ We,
                            const unsigned int* __restrict__ emask) {
    __shared__ float sW[DEDGE * H_N];
    __shared__ float sg[DEDGE], sb[DEDGE];
    int bid = blockIdx.x;
    if (bid < PREP_LN_BLKS) {
        // ---- LayerNorm(x) ----
        int warp = threadIdx.x >> 5, lane = threadIdx.x & 31;
        int tok  = bid * 8 + warp;
        const float* xp = x + (size_t)tok * 256 + lane * 8;
        float4 a0 = *(const float4*)xp;
        float4 a1 = *(const float4*)(xp + 4);
        float s  = a0.x + a0.y + a0.z + a0.w + a1.x + a1.y + a1.z + a1.w;
        float ss = a0.x*a0.x + a0.y*a0.y + a0.z*a0.z + a0.w*a0.w
                 + a1.x*a1.x + a1.y*a1.y + a1.z*a1.z + a1.w*a1.w;
        #pragma unroll
        for (int off = 16; off; off >>= 1) {
            s  += __shfl_xor_sync(0xffffffffu, s,  off);
            ss += __shfl_xor_sync(0xffffffffu, ss, off);
        }
        float mu  = s * (1.0f / 256.0f);
        float var = ss * (1.0f / 256.0f) - mu * mu;
        float rs  = rsqrtf(var + 1e-5f);
        float4 g0 = *(const float4*)(g + lane * 8);
        float4 g1 = *(const float4*)(g + lane * 8 + 4);
        float4 b0 = *(const float4*)(b + lane * 8);
        float4 b1 = *(const float4*)(b + lane * 8 + 4);
        float v[8];
        v[0] = (a0.x - mu) * rs * g0.x + b0.x;
        v[1] = (a0.y - mu) * rs * g0.y + b0.y;
        v[2] = (a0.z - mu) * rs * g0.z + b0.z;
        v[3] = (a0.w - mu) * rs * g0.w + b0.w;
        v[4] = (a1.x - mu) * rs * g1.x + b1.x;
        v[5] = (a1.y - mu) * rs * g1.y + b1.y;
        v[6] = (a1.z - mu) * rs * g1.z + b1.z;
        v[7] = (a1.w - mu) * rs * g1.w + b1.w;
        unsigned hu[4], lu[4];
        #pragma unroll
        for (int p = 0; p < 4; p++) split2(v[2 * p], v[2 * p + 1], hu[p], lu[p]);
        size_t off = (size_t)tok * 256 + lane * 8;
        *(uint4*)&g_xnh[off] = make_uint4(hu[0], hu[1], hu[2], hu[3]);
        *(uint4*)&g_xnl[off] = make_uint4(lu[0], lu[1], lu[2], lu[3]);
    } else if (bid < PREP_LN_BLKS + PREP_W_BLKS) {
        // ---- weight split ----
        int n = bid - PREP_LN_BLKS, k = threadIdx.x;
        float w;
        if (n < 256)       w = Wq [(size_t)k * 256 + n];
        else if (n < 768)  w = Wkv[(size_t)k * 512 + (n - 256)];
        else if (n < 1024) w = Wg [(size_t)k * 256 + (n - 768)];
        else               w = Wo [(size_t)k * 256 + (n - 1024)];
        __nv_bfloat16 h, l;
        split_bf16(w, h, l);
        if (n < 1024) {
            g_wph[(size_t)n * 256 + k] = h;
            g_wpl[(size_t)n * 256 + k] = l;
        } else {
            g_woh[(size_t)(n - 1024) * 256 + k] = h;
            g_wol[(size_t)(n - 1024) * 256 + k] = l;
        }
    } else {
        // ---- edge LN + W_edge + edge_mask -> fp16 bias [h][i][j] ----
        int t = threadIdx.x;
        for (int l = t; l < DEDGE * H_N; l += 256) sW[l] = We[l];
        if (t < DEDGE) { sg[t] = lg[t]; sb[t] = lb[t]; }
        __syncthreads();

        int warp = t >> 5, lane = t & 31;
        int p = (bid - PREP_LN_BLKS - PREP_W_BLKS) * 8 + warp;
        int i = p >> 8, j = p & 255;

        if (emask[p] == 0u) {
            if (lane < 8)
                g_bias[((size_t)(lane * 256 + i)) * 256 + j] = __float2half(-65504.0f);
            return;
        }
        const float* ep = edges + (size_t)p * DEDGE + lane * 4;
        float4 e = *(const float4*)ep;
        float s  = e.x + e.y + e.z + e.w;
        float ss = e.x*e.x + e.y*e.y + e.z*e.z + e.w*e.w;
        #pragma unroll
        for (int off = 16; off; off >>= 1) {
            s  += __shfl_xor_sync(0xffffffffu, s,  off);
            ss += __shfl_xor_sync(0xffffffffu, ss, off);
        }
        float mu  = s * (1.0f / 128.0f);
        float var = ss * (1.0f / 128.0f) - mu * mu;
        float rs  = rsqrtf(var + 1e-5f);
        int e0 = lane * 4;
        float en[4];
        en[0] = (e.x - mu) * rs * sg[e0 + 0] + sb[e0 + 0];
        en[1] = (e.y - mu) * rs * sg[e0 + 1] + sb[e0 + 1];
        en[2] = (e.z - mu) * rs * sg[e0 + 2] + sb[e0 + 2];
        en[3] = (e.w - mu) * rs * sg[e0 + 3] + sb[e0 + 3];
        float acc[8];
        #pragma unroll
        for (int h = 0; h < 8; h++) acc[h] = 0.0f;
        #pragma unroll
        for (int c = 0; c < 4; c++) {
            const float* wr = &sW[(e0 + c) * 8];
            #pragma unroll
            for (int h = 0; h < 8; h++) acc[h] += en[c] * wr[h];
        }
        #pragma unroll
        for (int h = 0; h < 8; h++) {
            #pragma unroll
            for (int off = 16; off; off >>= 1)
                acc[h] += __shfl_xor_sync(0xffffffffu, acc[h], off);
        }
        if (lane == 0) {
            #pragma unroll
            for (int h = 0; h < 8; h++)
                g_bias[((size_t)(h * 256 + i)) * 256 + j] = __float2half(acc[h]);
        }
    }
}

// ---------------- bf16x3 GEMM (ldmatrix + swizzle + 3-stage pipeline) ----------------
#define GEMM_SMEM()                                                            \
    __shared__ __nv_bfloat16 sAh[3][PLANE], sAl[3][PLANE];                     \
    __shared__ __nv_bfloat16 sBh[3][PLANE], sBl[3][PLANE];

#define GEMM_ISSUE(buf, kt, Ahp, Alp, Bhp, Blp, abase, nbase)                  \
    {                                                                          \
        int k0 = (kt) * 16 + ch;                                               \
        unsigned doff = ((unsigned)(buf) * PLANE + row * RS + chsw) * 2;       \
        CP16(sAh_u + doff, (Ahp) + (size_t)((abase) + row) * 256 + k0);        \
        CP16(sAl_u + doff, (Alp) + (size_t)((abase) + row) * 256 + k0);        \
        CP16(sBh_u + doff, (Bhp) + (size_t)((nbase) + row) * 256 + k0);        \
        CP16(sBl_u + doff, (Blp) + (size_t)((nbase) + row) * 256 + k0);        \
        cp_commit();                                                           \
    }

#define GEMM_LANEOFF()                                                         \
    int arow  = (lane & 7) + ((lane >> 3) & 1) * 8;                            \
    int achnk = ((lane >> 4) * 8) ^ ((arow & 4) << 1);                         \
    int brow  = (lane & 7) + ((lane >> 4) & 1) * 8;                            \
    int bchnk = (((lane >> 3) & 1) * 8) ^ ((brow & 4) << 1);

#define GEMM_KTILE(st)                                                         \
    {                                                                          \
        unsigned stoff = (unsigned)(st) * PLANE * 2;                           \
        unsigned bh[4][2], bl[4][2];                                           \
        _Pragma("unroll")                                                      \
        for (int p = 0; p < 2; p++) {                                          \
            unsigned bo = ((wn * 32 + p * 16 + brow) * RS + bchnk) * 2;        \
            LDSM4(bh[2*p][0], bh[2*p][1], bh[2*p+1][0], bh[2*p+1][1],          \
                  sBh_u + stoff + bo)                                          \
            LDSM4(bl[2*p][0], bl[2*p][1], bl[2*p+1][0], bl[2*p+1][1],          \
                  sBl_u + stoff + bo)                                          \
        }                                                                      \
        _Pragma("unroll")                                                      \
        for (int am = 0; am < 4; am++) {                                       \
            unsigned ao = ((wm * 64 + am * 16 + arow) * RS + achnk) * 2;       \
            unsigned ah0, ah1, ah2, ah3, al0, al1, al2, al3;                   \
            LDSM4(ah0, ah1, ah2, ah3, sAh_u + stoff + ao)                      \
            LDSM4(al0, al1, al2, al3, sAl_u + stoff + ao)                      \
            _Pragma("unroll")                                                  \
            for (int an = 0; an < 4; an++) {                                   \
                float* ac = acc[am][an];                                       \
                mma_bf16(ac, ah0, ah1, ah2, ah3, bh[an][0], bh[an][1]);        \
                mma_bf16(ac, ah0, ah1, ah2, ah3, bl[an][0], bl[an][1]);        \
                mma_bf16(ac, al0, al1, al2, al3, bh[an][0], bh[an][1]);        \
            }                                                                  \
        }                                                                      \
    }

#define GEMM_MAINLOOP(Ahp, Alp, Bhp, Blp, abase, nbase)                        \
    GEMM_ISSUE(0, 0, Ahp, Alp, Bhp, Blp, abase, nbase)                         \
    GEMM_ISSUE(1, 1, Ahp, Alp, Bhp, Blp, abase, nbase)                         \
    for (int kt = 0; kt < 16; kt++) {                                          \
        if (kt < 15) cp_wait1(); else cp_wait0();                              \
        __syncthreads();                                                       \
        if (kt <= 13) {                                                        \
            int nbuf = (kt + 2) % 3;                                           \
            GEMM_ISSUE(nbuf, kt + 2, Ahp, Alp, Bhp, Blp, abase, nbase)         \
        }                                                                      \
        GEMM_KTILE(kt % 3)                                                     \
    }

// ---------------- kernel 3: projection GEMM (bf16x3) ----------------
__global__ void __launch_bounds__(256, 2)
proj_mma(const float* __restrict__ bg) {
    GEMM_SMEM()
    int t = threadIdx.x, lane = t & 31, warp = t >> 5;
    int wm = warp >> 2, wn = warp & 3;
    int g = lane >> 2, c = lane & 3;
    int bn = blockIdx.x, bm = blockIdx.y;
    int nb = bn * 128;
    int abase = bm * 128;

    unsigned sAh_u = (unsigned)__cvta_generic_to_shared(sAh);
    unsigned sAl_u = (unsigned)__cvta_generic_to_shared(sAl);
    unsigned sBh_u = (unsigned)__cvta_generic_to_shared(sBh);
    unsigned sBl_u = (unsigned)__cvta_generic_to_shared(sBl);
    int row = t >> 1, ch = (t & 1) * 8;
    int chsw = ch ^ ((row & 4) << 1);
    GEMM_LANEOFF()

    float acc[4][4][4];
    #pragma unroll
    for (int am = 0; am < 4; am++)
        #pragma unroll
        for (int an = 0; an < 4; an++)
            #pragma unroll
            for (int v = 0; v < 4; v++) acc[am][an][v] = 0.0f;

    GEMM_MAINLOOP(g_xnh, g_xnl, g_wph, g_wpl, abase, nb)

    #pragma unroll
    for (int am = 0; am < 4; am++) {
        int tok = abase + wm * 64 + am * 16 + g;
        int rr = tok >> 8, iw = tok & 255;
        #pragma unroll
        for (int an = 0; an < 4; an++) {
            int gc = nb + wn * 32 + an * 8 + 2 * c;
            float a0 = acc[am][an][0], a1 = acc[am][an][1];
            float a2 = acc[am][an][2], a3 = acc[am][an][3];
            if (gc < 256) {                       // q: fp32, [rh][i][d]
                int hh = gc >> 5, d8 = gc & 31;
                float* p0 = g_q + ((size_t)((rr * 8 + hh) * 256 + iw)) * 32 + d8;
                *(float2*)p0            = make_float2(a0, a1);
                *(float2*)(p0 + 8 * 32) = make_float2(a2, a3);
            } else if (gc < 512) {                // k: bf16 split, [rh][j][d]
                int cq = gc - 256;
                int hh = cq >> 5, d8 = cq & 31;
                size_t b0 = ((size_t)((rr * 8 + hh) * 256 + iw)) * 32 + d8;
                unsigned hi0, lo0, hi1, lo1;
                split2(a0, a1, hi0, lo0);
                split2(a2, a3, hi1, lo1);
                *(unsigned*)&g_kh[b0] = hi0;  *(unsigned*)&g_kl[b0] = lo0;
                *(unsigned*)&g_kh[b0 + 256] = hi1;  *(unsigned*)&g_kl[b0 + 256] = lo1;
            } else if (gc < 768) {                // v: bf16 split, transposed [rh][d][j]
                int cq = gc - 512;
                int hh = cq >> 5, d8 = cq & 31;
                size_t vb = ((size_t)((rr * 8 + hh) * 32 + d8)) * 256 + iw;
                __nv_bfloat16 h0, l0, h1, l1;
                split_bf16(a0, h0, l0);  g_vh[vb] = h0;        g_vl[vb] = l0;
                split_bf16(a1, h1, l1);  g_vh[vb + 256] = h1;  g_vl[vb + 256] = l1;
                split_bf16(a2, h0, l0);  g_vh[vb + 8] = h0;    g_vl[vb + 8] = l0;
                split_bf16(a3, h1, l1);  g_vh[vb + 264] = h1;  g_vl[vb + 264] = l1;
            } else {                              // gate: sigmoid fp32
                int gcol = gc - 768;
                float2 bg2 = *(const float2*)(bg + gcol);
                float* p0 = g_gate + (size_t)tok * 256 + gcol;
                float* p1 = p0 + 8 * 256;
                *(float2*)p0 = make_float2(1.0f / (1.0f + __expf(-(a0 + bg2.x))),
                                           1.0f / (1.0f + __expf(-(a1 + bg2.y))));
                *(float2*)p1 = make_float2(1.0f / (1.0f + __expf(-(a2 + bg2.x))),
                                           1.0f / (1.0f + __expf(-(a3 + bg2.y))));
            }
        }
    }
}

// ---------------- kernel 5: output projection (bf16x3) ----------------
__global__ void __launch_bounds__(256, 2)
out_mma(const float* __restrict__ bo, float* __restrict__ out) {
    GEMM_SMEM()
    int t = threadIdx.x, lane = t & 31, warp = t >> 5;
    int wm = warp >> 2, wn = warp & 3;
    int g = lane >> 2, c = lane & 3;
    int bn = blockIdx.x, bm = blockIdx.y;
    int nb = bn * 128;
    int abase = bm * 128;

    unsigned sAh_u = (unsigned)__cvta_generic_to_shared(sAh);
    unsigned sAl_u = (unsigned)__cvta_generic_to_shared(sAl);
    unsigned sBh_u = (unsigned)__cvta_generic_to_shared(sBh);
    unsigned sBl_u = (unsigned)__cvta_generic_to_shared(sBl);
    int row = t >> 1, ch = (t & 1) * 8;
    int chsw = ch ^ ((row & 4) << 1);
    GEMM_LANEOFF()

    float acc[4][4][4];
    #pragma unroll
    for (int am = 0; am < 4; am++)
        #pragma unroll
        for (int an = 0; an < 4; an++)
            #pragma unroll
            for (int v = 0; v < 4; v++) acc[am][an][v] = 0.0f;

    GEMM_MAINLOOP(g_atth, g_attl, g_woh, g_wol, abase, nb)

    #pragma unroll
    for (int am = 0; am < 4; am++) {
        int tok = abase + wm * 64 + am * 16 + g;
        #pragma unroll
        for (int an = 0; an < 4; an++) {
            int gc = nb + wn * 32 + an * 8 + 2 * c;
            float2 bo2 = *(const float2*)(bo + gc);
            float* p0 = out + (size_t)tok * 256 + gc;
            float* p1 = p0 + 8 * 256;
            *(float2*)p0 = make_float2(acc[am][an][0] + bo2.x, acc[am][an][1] + bo2.y);
            *(float2*)p1 = make_float2(acc[am][an][2] + bo2.x, acc[am][an][3] + bo2.y);
        }
    }
}

// ---------------- kernel 4: attention via bf16x3 mma.sync (16 warps, 16 q/warp) ----
// bias read from gmem with one-chunk register prefetch; KV staged via cp.async
#define A_K_OFF   0
#define A_KL_OFF  2560                // 32 rows * 80 B per plane
#define A_VH_OFF  5120
#define A_VL_OFF  7680
#define A_STAGE   10240
#define A_SMEM    (3 * A_STAGE)       // 30720

__global__ void __launch_bounds__(512, 1)
attn_mma(const unsigned int* __restrict__ mask) {
    extern __shared__ char asmem[];
    __shared__ unsigned mwords[8];

    int t = threadIdx.x, lane = t & 31, w = t >> 5;   // w = 0..15
    int g = lane >> 2, c = lane & 3;
    int rh = blockIdx.x;
    int r = rh >> 3, h = rh & 7;
    unsigned smem_u = (unsigned)__cvta_generic_to_shared(asmem);

    // key-mask ballot words
    if (w == 0) {
        #pragma unroll
        for (int q = 0; q < 8; q++) {
            unsigned bit = (mask[r * 256 + q * 32 + lane] != 0u) ? 1u : 0u;
            unsigned word = __ballot_sync(0xffffffffu, bit);
            if (lane == 0) mwords[q] = word;
        }
    }

    const float sc = 0.17677669529663689f;   // 32^-0.5
    int i0 = w * 16 + g, i1 = i0 + 8;
    int rowv0 = (mask[r * 256 + i0] != 0u);
    int rowv1 = (mask[r * 256 + i1] != 0u);

    // Q fragments (scaled, split)
    unsigned qh[2][4], ql[2][4];
    {
        const float* q0 = g_q + ((size_t)rh * 256 + i0) * 32;
        const float* q1 = g_q + ((size_t)rh * 256 + i1) * 32;
        #pragma unroll
        for (int ks = 0; ks < 2; ks++) {
            float2 x0 = *(const float2*)(q0 + ks * 16 + 2 * c);
            float2 x1 = *(const float2*)(q1 + ks * 16 + 2 * c);
            float2 x2 = *(const float2*)(q0 + ks * 16 + 2 * c + 8);
            float2 x3 = *(const float2*)(q1 + ks * 16 + 2 * c + 8);
            split2(x0.x * sc, x0.y * sc, qh[ks][0], ql[ks][0]);
            split2(x1.x * sc, x1.y * sc, qh[ks][1], ql[ks][1]);
            split2(x2.x * sc, x2.y * sc, qh[ks][2], ql[ks][2]);
            split2(x3.x * sc, x3.y * sc, qh[ks][3], ql[ks][3]);
        }
    }

    float O[4][4];
    float l0 = 0.0f, l1 = 0.0f;
    #pragma unroll
    for (int dt = 0; dt < 4; dt++)
        #pragma unroll
        for (int v = 0; v < 4; v++) O[dt][v] = 0.0f;

    // bias row pointers ([h][i][j] layout, half2 at even j)
    const __half2* bR0 = (const __half2*)&g_bias[((size_t)(h * 256 + i0)) * 256 + 2 * c];
    const __half2* bR1 = (const __half2*)&g_bias[((size_t)(h * 256 + i1)) * 256 + 2 * c];

    const __nv_bfloat16* khb = g_kh + (size_t)rh * 256 * 32;
    const __nv_bfloat16* klb = g_kl + (size_t)rh * 256 * 32;
    const __nv_bfloat16* vhb = g_vh + (size_t)rh * 32 * 256;
    const __nv_bfloat16* vlb = g_vl + (size_t)rh * 32 * 256;

    // per-chunk cp.async (512 threads): exactly 1 KV 16B chunk per thread
    int kvp  = t >> 7;                 // plane 0..3
    int kvr  = (t >> 2) & 31;          // row 0..31
    int kvs  = t & 3;                  // 16B chunk within 64B row

    #define AISSUE(chv)                                                            \
    {                                                                              \
        unsigned sb = smem_u + (unsigned)((chv) % 3) * A_STAGE;                    \
        unsigned kvo = sb + (unsigned)kvp * 2560 + kvr * 80 + kvs * 16;            \
        if (kvp == 0)                                                              \
            CP16(kvo, khb + (size_t)((chv) * 32 + kvr) * 32 + kvs * 8);            \
        else if (kvp == 1)                                                         \
            CP16(kvo, klb + (size_t)((chv) * 32 + kvr) * 32 + kvs * 8);            \
        else if (kvp == 2)                                                         \
            CP16(kvo, vhb + (size_t)kvr * 256 + (chv) * 32 + kvs * 8);             \
        else                                                                       \
            CP16(kvo, vlb + (size_t)kvr * 256 + (chv) * 32 + kvs * 8);             \
        cp_commit();                                                               \
    }

    AISSUE(0)
    AISSUE(1)

    // prefetch bias registers for chunk 0
    __half2 bv0[4], bv1[4];
    #pragma unroll
    for (int jt = 0; jt < 4; jt++) {
        bv0[jt] = bR0[jt * 4];
        bv1[jt] = bR1[jt * 4];
    }

    int brow = (lane & 7) + ((lane >> 4) & 1) * 8;
    int bch  = ((lane >> 3) & 1) * 8;

    for (int chk = 0; chk < 8; chk++) {
        if (chk < 7) cp_wait1(); else cp_wait0();
        __syncthreads();
        if (chk + 2 < 8) AISSUE(chk + 2)

        // consume prefetched bias; immediately prefetch next chunk's bias
        __half2 cb0[4], cb1[4];
        #pragma unroll
        for (int jt = 0; jt < 4; jt++) { cb0[jt] = bv0[jt]; cb1[jt] = bv1[jt]; }
        if (chk < 7) {
            #pragma unroll
            for (int jt = 0; jt < 4; jt++) {
                bv0[jt] = bR0[(chk + 1) * 16 + jt * 4];
                bv1[jt] = bR1[(chk + 1) * 16 + jt * 4];
            }
        }

        int st = chk % 3;
        unsigned sb = smem_u + (unsigned)st * A_STAGE;

        // K fragments
        unsigned kfh[2][4][2], kfl[2][4][2];
        #pragma unroll
        for (int p = 0; p < 2; p++) {
            #pragma unroll
            for (int ks = 0; ks < 2; ks++) {
                unsigned ao = sb + A_K_OFF + (p * 16 + brow) * 80 + (ks * 16 + bch) * 2;
                LDSM4(kfh[ks][2*p][0], kfh[ks][2*p][1], kfh[ks][2*p+1][0], kfh[ks][2*p+1][1], ao)
                unsigned al_ = sb + A_KL_OFF + (p * 16 + brow) * 80 + (ks * 16 + bch) * 2;
                LDSM4(kfl[ks][2*p][0], kfl[ks][2*p][1], kfl[ks][2*p+1][0], kfl[ks][2*p+1][1], al_)
            }
        }

        // S = (q*sc) @ K^T  (bf16x3)
        float S[4][4];
        #pragma unroll
        for (int jt = 0; jt < 4; jt++) {
            #pragma unroll
            for (int v = 0; v < 4; v++) S[jt][v] = 0.0f;
            #pragma unroll
            for (int ks = 0; ks < 2; ks++) {
                mma_bf16(S[jt], qh[ks][0], qh[ks][1], qh[ks][2], qh[ks][3],
                         kfh[ks][jt][0], kfh[ks][jt][1]);
                mma_bf16(S[jt], qh[ks][0], qh[ks][1], qh[ks][2], qh[ks][3],
                         kfl[ks][jt][0], kfl[ks][jt][1]);
                mma_bf16(S[jt], ql[ks][0], ql[ks][1], ql[ks][2], ql[ks][3],
                         kfh[ks][jt][0], kfh[ks][jt][1]);
            }
        }

        // bias + mask + exp
        unsigned mb = mwords[chk];
        #pragma unroll
        for (int jt = 0; jt < 4; jt++) {
            int j0 = jt * 8 + 2 * c;
            float2 f0 = __half22float2(cb0[jt]);
            float2 f1 = __half22float2(cb1[jt]);
            unsigned jm0 = (mb >> j0) & 1u, jm1 = (mb >> (j0 + 1)) & 1u;
            float p00 = jm0 ? __expf(S[jt][0] + f0.x) : 0.0f;
            float p01 = jm1 ? __expf(S[jt][1] + f0.y) : 0.0f;
            float p10 = jm0 ? __expf(S[jt][2] + f1.x) : 0.0f;
            float p11 = jm1 ? __expf(S[jt][3] + f1.y) : 0.0f;
            if (!rowv0) { p00 = 1.0f; p01 = 1.0f; }
            if (!rowv1) { p10 = 1.0f; p11 = 1.0f; }
            l0 += p00 + p01;
            l1 += p10 + p11;
            S[jt][0] = p00; S[jt][1] = p01;
            S[jt][2] = p10; S[jt][3] = p11;
        }

        // O += P @ V  (P split exactly; V split)
        #pragma unroll
        for (int ks = 0; ks < 2; ks++) {
            unsigned vfh[4][2], vfl[4][2];
            #pragma unroll
            for (int p = 0; p < 2; p++) {
                unsigned ao = sb + A_VH_OFF + (p * 16 + brow) * 80 + (ks * 16 + bch) * 2;
                LDSM4(vfh[2*p][0], vfh[2*p][1], vfh[2*p+1][0], vfh[2*p+1][1], ao)
                unsigned al_ = sb + A_VL_OFF + (p * 16 + brow) * 80 + (ks * 16 + bch) * 2;
                LDSM4(vfl[2*p][0], vfl[2*p][1], vfl[2*p+1][0], vfl[2*p+1][1], al_)
            }
            const float* PA = S[2 * ks];
            const float* PB = S[2 * ks + 1];
            unsigned ah0, ah1, ah2, ah3, al0, al1, al2, al3;
            split2(PA[0], PA[1], ah0, al0);
            split2(PA[2], PA[3], ah1, al1);
            split2(PB[0], PB[1], ah2, al2);
            split2(PB[2], PB[3], ah3, al3);
            #pragma unroll
            for (int dt = 0; dt < 4; dt++) {
                mma_bf16(O[dt], ah0, ah1, ah2, ah3, vfh[dt][0], vfh[dt][1]);
                mma_bf16(O[dt], ah0, ah1, ah2, ah3, vfl[dt][0], vfl[dt][1]);
                mma_bf16(O[dt], al0, al1, al2, al3, vfh[dt][0], vfh[dt][1]);
            }
        }
    }
    #undef AISSUE

    // finalize: reduce l over quad, normalize, gate, split-store
    l0 += __shfl_xor_sync(0xffffffffu, l0, 1);
    l0 += __shfl_xor_sync(0xffffffffu, l0, 2);
    l1 += __shfl_xor_sync(0xffffffffu, l1, 1);
    l1 += __shfl_xor_sync(0xffffffffu, l1, 2);
    float inv0 = 1.0f / l0;
    float inv1 = 1.0f / l1;

    int tok0 = r * 256 + i0;
    int tok1 = r * 256 + i1;
    #pragma unroll
    for (int dt = 0; dt < 4; dt++) {
        int col = h * 32 + dt * 8 + 2 * c;
        float2 g0 = *(const float2*)&g_gate[(size_t)tok0 * 256 + col];
        float2 g1 = *(const float2*)&g_gate[(size_t)tok1 * 256 + col];
        float o00 = O[dt][0] * inv0 * g0.x;
        float o01 = O[dt][1] * inv0 * g0.y;
        float o10 = O[dt][2] * inv1 * g1.x;
        float o11 = O[dt][3] * inv1 * g1.y;
        unsigned hi0, lo0, hi1, lo1;
        split2(o00, o01, hi0, lo0);
        split2(o10, o11, hi1, lo1);
        *(unsigned*)&g_atth[(size_t)tok0 * 256 + col] = hi0;
        *(unsigned*)&g_attl[(size_t)tok0 * 256 + col] = lo0;
        *(unsigned*)&g_atth[(size_t)tok1 * 256 + col] = hi1;
        *(unsigned*)&g_attl[(size_t)tok1 * 256 + col] = lo1;
    }
}

// ---------------- launch ----------------
extern "C" void kernel_launch(void* const* d_in, const int* in_sizes, int n_in,
                              void* d_out, int out_size) {
    const float* x      = (const float*)d_in[0];
    const float* edges  = (const float*)d_in[1];
    const unsigned int* mask      = (const unsigned int*)d_in[2];
    const unsigned int* edge_mask = (const unsigned int*)d_in[3];
    const float* ln_g   = (const float*)d_in[4];
    const float* ln_b   = (const float*)d_in[5];
    const float* lne_g  = (const float*)d_in[6];
    const float* lne_b  = (const float*)d_in[7];
    const float* W_edge = (const float*)d_in[8];
    const float* Wq     = (const float*)d_in[9];
    const float* Wkv    = (const float*)d_in[10];
    const float* Wg     = (const float*)d_in[11];
    const float* bg     = (const float*)d_in[12];
    const float* Wo     = (const float*)d_in[13];
    const float* bo     = (const float*)d_in[14];
    float* out = (float*)d_out;

    cudaFuncSetAttribute(attn_mma, cudaFuncAttributeMaxDynamicSharedMemorySize, A_SMEM);

    prep_kernel<<<PREP_LN_BLKS + PREP_W_BLKS + PREP_BIAS_BLKS, 256>>>(
        x, ln_g, ln_b, Wq, Wkv, Wg, Wo, edges, lne_g, lne_b, W_edge, edge_mask);
    proj_mma<<<dim3(8, NTOK / 128), 256>>>(bg);
    attn_mma<<<R_DIM * H_N, 512, A_SMEM>>>(mask);
    out_mma<<<dim3(2, NTOK / 128), 256>>>(bo, out);
}

// round 17
// speedup vs baseline: 1.1963x; 1.1148x over previous
#include <cuda_runtime.h>
#include <cuda_bf16.h>
#include <cuda_fp16.h>

// Problem constants
#define R_DIM 128
#define W_DIM 256
#define DNODE 256
#define DEDGE 128
#define H_N   8
#define DHEAD 32
#define NTOK  (R_DIM * W_DIM)       // 32768
#define NEGMAX (-3.4028234663852886e38f)

// ---------------- scratch (device globals: allocation-free) ----------------
__device__ float g_q   [NTOK * DNODE];          // [rh][i][32] fp32 (unscaled)
__device__ float g_gate[NTOK * DNODE];
__device__ __half g_bias[H_N * W_DIM * W_DIM];  // [h][i][j], fp16 (masked = -65504)
// fp16 activation split planes (hi + lo ~= fp32) for proj
__device__ __half g_xnh [NTOK * DNODE];
__device__ __half g_xnl [NTOK * DNODE];
__device__ __half g_wph [1024 * 256];           // proj weights fp16 [n][k]
// bf16 split planes for out projection
__device__ __nv_bfloat16 g_atth[NTOK * DNODE];
__device__ __nv_bfloat16 g_attl[NTOK * DNODE];
__device__ __nv_bfloat16 g_woh [256 * 256];
__device__ __nv_bfloat16 g_wol [256 * 256];
__device__ __nv_bfloat16 g_kh  [NTOK * DNODE];  // [rh][j][32d]
__device__ __nv_bfloat16 g_kl  [NTOK * DNODE];
__device__ __nv_bfloat16 g_vh  [NTOK * DNODE];  // [rh][32d][256j] (transposed)
__device__ __nv_bfloat16 g_vl  [NTOK * DNODE];

// ---------------- helpers ----------------
__device__ __forceinline__ void mma_bf16(float* d,
                                         unsigned a0, unsigned a1, unsigned a2, unsigned a3,
                                         unsigned b0, unsigned b1) {
    asm volatile(
        "mma.sync.aligned.m16n8k16.row.col.f32.bf16.bf16.f32 "
        "{%0,%1,%2,%3}, {%4,%5,%6,%7}, {%8,%9}, {%0,%1,%2,%3};"
        : "+f"(d[0]), "+f"(d[1]), "+f"(d[2]), "+f"(d[3])
        : "r"(a0), "r"(a1), "r"(a2), "r"(a3), "r"(b0), "r"(b1));
}
__device__ __forceinline__ void mma_f16(float* d,
                                        unsigned a0, unsigned a1, unsigned a2, unsigned a3,
                                        unsigned b0, unsigned b1) {
    asm volatile(
        "mma.sync.aligned.m16n8k16.row.col.f32.f16.f16.f32 "
        "{%0,%1,%2,%3}, {%4,%5,%6,%7}, {%8,%9}, {%0,%1,%2,%3};"
        : "+f"(d[0]), "+f"(d[1]), "+f"(d[2]), "+f"(d[3])
        : "r"(a0), "r"(a1), "r"(a2), "r"(a3), "r"(b0), "r"(b1));
}
__device__ __forceinline__ void split_bf16(float x, __nv_bfloat16& hi, __nv_bfloat16& lo) {
    hi = __float2bfloat16(x);
    lo = __float2bfloat16(x - __bfloat162float(hi));
}
__device__ __forceinline__ unsigned bfpack(__nv_bfloat16 a, __nv_bfloat16 b) {
    return (unsigned)__bfloat16_as_ushort(a) | ((unsigned)__bfloat16_as_ushort(b) << 16);
}
__device__ __forceinline__ void split2(float a, float b, unsigned& hi, unsigned& lo) {
    __nv_bfloat16 ha, la, hb, lb;
    split_bf16(a, ha, la);
    split_bf16(b, hb, lb);
    hi = bfpack(ha, hb);
    lo = bfpack(la, lb);
}
__device__ __forceinline__ unsigned hpack(__half a, __half b) {
    return (unsigned)__half_as_ushort(a) | ((unsigned)__half_as_ushort(b) << 16);
}
__device__ __forceinline__ void split2h(float a, float b, unsigned& hi, unsigned& lo) {
    __half ha = __float2half(a);
    __half hb = __float2half(b);
    __half la = __float2half(a - __half2float(ha));
    __half lb = __float2half(b - __half2float(hb));
    hi = hpack(ha, hb);
    lo = hpack(la, lb);
}
#define CP16(dst_u32, src_ptr) \
    asm volatile("cp.async.ca.shared.global [%0], [%1], 16;" :: "r"(dst_u32), "l"(src_ptr))
__device__ __forceinline__ void cp_commit() { asm volatile("cp.async.commit_group;"); }
__device__ __forceinline__ void cp_wait0()  { asm volatile("cp.async.wait_group 0;"); }
__device__ __forceinline__ void cp_wait1()  { asm volatile("cp.async.wait_group 1;"); }
#define LDSM4(r0, r1, r2, r3, addr) \
    asm volatile("ldmatrix.sync.aligned.m8n8.x4.shared.b16 {%0,%1,%2,%3}, [%4];" \
        : "=r"(r0), "=r"(r1), "=r"(r2), "=r"(r3) : "r"(addr));

// GEMM smem: RS=16 (no pad), XOR swizzle (chunk ^= (row&4)<<1)
#define RS 16
#define PLANE (128 * RS)

// ---------------- kernel 1 (fused): LN(x) + weight split + edge bias ----------
#define PREP_LN_BLKS   (NTOK / 8)            // 4096
#define PREP_W_BLKS    1280
#define PREP_BIAS_BLKS ((W_DIM * W_DIM) / 8) // 8192
__global__ void prep_kernel(const float* __restrict__ x,
                            const float* __restrict__ g,
                            const float* __restrict__ b,
                            const float* __restrict__ Wq, const float* __restrict__ Wkv,
                            const float* __restrict__ Wg, const float* __restrict__ Wo,
                            const float* __restrict__ edges,
                            const float* __restrict__ lg,
                            const float* __restrict__ lb,
                            const float* __restrict__ We,
                            const unsigned int* __restrict__ emask) {
    __shared__ float sW[DEDGE * H_N];
    __shared__ float sg[DEDGE], sb[DEDGE];
    int bid = blockIdx.x;
    if (bid < PREP_LN_BLKS) {
        // ---- LayerNorm(x) -> fp16 hi/lo planes ----
        int warp = threadIdx.x >> 5, lane = threadIdx.x & 31;
        int tok  = bid * 8 + warp;
        const float* xp = x + (size_t)tok * 256 + lane * 8;
        float4 a0 = *(const float4*)xp;
        float4 a1 = *(const float4*)(xp + 4);
        float s  = a0.x + a0.y + a0.z + a0.w + a1.x + a1.y + a1.z + a1.w;
        float ss = a0.x*a0.x + a0.y*a0.y + a0.z*a0.z + a0.w*a0.w
                 + a1.x*a1.x + a1.y*a1.y + a1.z*a1.z + a1.w*a1.w;
        #pragma unroll
        for (int off = 16; off; off >>= 1) {
            s  += __shfl_xor_sync(0xffffffffu, s,  off);
            ss += __shfl_xor_sync(0xffffffffu, ss, off);
        }
        float mu  = s * (1.0f / 256.0f);
        float var = ss * (1.0f / 256.0f) - mu * mu;
        float rs  = rsqrtf(var + 1e-5f);
        float4 g0 = *(const float4*)(g + lane * 8);
        float4 g1 = *(const float4*)(g + lane * 8 + 4);
        float4 b0 = *(const float4*)(b + lane * 8);
        float4 b1 = *(const float4*)(b + lane * 8 + 4);
        float v[8];
        v[0] = (a0.x - mu) * rs * g0.x + b0.x;
        v[1] = (a0.y - mu) * rs * g0.y + b0.y;
        v[2] = (a0.z - mu) * rs * g0.z + b0.z;
        v[3] = (a0.w - mu) * rs * g0.w + b0.w;
        v[4] = (a1.x - mu) * rs * g1.x + b1.x;
        v[5] = (a1.y - mu) * rs * g1.y + b1.y;
        v[6] = (a1.z - mu) * rs * g1.z + b1.z;
        v[7] = (a1.w - mu) * rs * g1.w + b1.w;
        unsigned hu[4], lu[4];
        #pragma unroll
        for (int p = 0; p < 4; p++) split2h(v[2 * p], v[2 * p + 1], hu[p], lu[p]);
        size_t off = (size_t)tok * 256 + lane * 8;
        *(uint4*)&g_xnh[off] = make_uint4(hu[0], hu[1], hu[2], hu[3]);
        *(uint4*)&g_xnl[off] = make_uint4(lu[0], lu[1], lu[2], lu[3]);
    } else if (bid < PREP_LN_BLKS + PREP_W_BLKS) {
        // ---- weight split: proj weights -> fp16; Wo -> bf16 hi/lo ----
        int n = bid - PREP_LN_BLKS, k = threadIdx.x;
        float w;
        if (n < 256)       w = Wq [(size_t)k * 256 + n];
        else if (n < 768)  w = Wkv[(size_t)k * 512 + (n - 256)];
        else if (n < 1024) w = Wg [(size_t)k * 256 + (n - 768)];
        else               w = Wo [(size_t)k * 256 + (n - 1024)];
        if (n < 1024) {
            g_wph[(size_t)n * 256 + k] = __float2half(w);
        } else {
            __nv_bfloat16 h, l;
            split_bf16(w, h, l);
            g_woh[(size_t)(n - 1024) * 256 + k] = h;
            g_wol[(size_t)(n - 1024) * 256 + k] = l;
        }
    } else {
        // ---- edge LN + W_edge + edge_mask -> fp16 bias [h][i][j] ----
        int t = threadIdx.x;
        for (int l = t; l < DEDGE * H_N; l += 256) sW[l] = We[l];
        if (t < DEDGE) { sg[t] = lg[t]; sb[t] = lb[t]; }
        __syncthreads();

        int warp = t >> 5, lane = t & 31;
        int p = (bid - PREP_LN_BLKS - PREP_W_BLKS) * 8 + warp;
        int i = p >> 8, j = p & 255;

        if (emask[p] == 0u) {
            if (lane < 8)
                g_bias[((size_t)(lane * 256 + i)) * 256 + j] = __float2half(-65504.0f);
            return;
        }
        const float* ep = edges + (size_t)p * DEDGE + lane * 4;
        float4 e = *(const float4*)ep;
        float s  = e.x + e.y + e.z + e.w;
        float ss = e.x*e.x + e.y*e.y + e.z*e.z + e.w*e.w;
        #pragma unroll
        for (int off = 16; off; off >>= 1) {
            s  += __shfl_xor_sync(0xffffffffu, s,  off);
            ss += __shfl_xor_sync(0xffffffffu, ss, off);
        }
        float mu  = s * (1.0f / 128.0f);
        float var = ss * (1.0f / 128.0f) - mu * mu;
        float rs  = rsqrtf(var + 1e-5f);
        int e0 = lane * 4;
        float en[4];
        en[0] = (e.x - mu) * rs * sg[e0 + 0] + sb[e0 + 0];
        en[1] = (e.y - mu) * rs * sg[e0 + 1] + sb[e0 + 1];
        en[2] = (e.z - mu) * rs * sg[e0 + 2] + sb[e0 + 2];
        en[3] = (e.w - mu) * rs * sg[e0 + 3] + sb[e0 + 3];
        float acc[8];
        #pragma unroll
        for (int h = 0; h < 8; h++) acc[h] = 0.0f;
        #pragma unroll
        for (int c = 0; c < 4; c++) {
            const float* wr = &sW[(e0 + c) * 8];
            #pragma unroll
            for (int h = 0; h < 8; h++) acc[h] += en[c] * wr[h];
        }
        #pragma unroll
        for (int h = 0; h < 8; h++) {
            #pragma unroll
            for (int off = 16; off; off >>= 1)
                acc[h] += __shfl_xor_sync(0xffffffffu, acc[h], off);
        }
        if (lane == 0) {
            #pragma unroll
            for (int h = 0; h < 8; h++)
                g_bias[((size_t)(h * 256 + i)) * 256 + j] = __float2half(acc[h]);
        }
    }
}

// ---------------- shared lane-offset computation ----------------
#define GEMM_LANEOFF()                                                         \
    int arow  = (lane & 7) + ((lane >> 3) & 1) * 8;                            \
    int achnk = ((lane >> 4) * 8) ^ ((arow & 4) << 1);                         \
    int brow  = (lane & 7) + ((lane >> 4) & 1) * 8;                            \
    int bchnk = (((lane >> 3) & 1) * 8) ^ ((brow & 4) << 1);

// ---------------- kernel 3: projection GEMM (fp16x2: Ah,Al x Bh) ----------------
#define PROJ_ISSUE(buf, kt)                                                    \
    {                                                                          \
        int k0 = (kt) * 16 + ch;                                               \
        unsigned doff = ((unsigned)(buf) * PLANE + row * RS + chsw) * 2;       \
        CP16(pAh_u + doff, g_xnh + (size_t)(abase + row) * 256 + k0);          \
        CP16(pAl_u + doff, g_xnl + (size_t)(abase + row) * 256 + k0);          \
        CP16(pBh_u + doff, g_wph + (size_t)(nb + row) * 256 + k0);             \
        cp_commit();                                                           \
    }

#define PROJ_KTILE(st)                                                         \
    {                                                                          \
        unsigned stoff = (unsigned)(st) * PLANE * 2;                           \
        unsigned bh[4][2];                                                     \
        _Pragma("unroll")                                                      \
        for (int p = 0; p < 2; p++) {                                          \
            unsigned bo = ((wn * 32 + p * 16 + brow) * RS + bchnk) * 2;        \
            LDSM4(bh[2*p][0], bh[2*p][1], bh[2*p+1][0], bh[2*p+1][1],          \
                  pBh_u + stoff + bo)                                          \
        }                                                                      \
        _Pragma("unroll")                                                      \
        for (int am = 0; am < 4; am++) {                                       \
            unsigned ao = ((wm * 64 + am * 16 + arow) * RS + achnk) * 2;       \
            unsigned ah0, ah1, ah2, ah3, al0, al1, al2, al3;                   \
            LDSM4(ah0, ah1, ah2, ah3, pAh_u + stoff + ao)                      \
            LDSM4(al0, al1, al2, al3, pAl_u + stoff + ao)                      \
            _Pragma("unroll")                                                  \
            for (int an = 0; an < 4; an++) {                                   \
                float* ac = acc[am][an];                                       \
                mma_f16(ac, ah0, ah1, ah2, ah3, bh[an][0], bh[an][1]);         \
                mma_f16(ac, al0, al1, al2, al3, bh[an][0], bh[an][1]);         \
            }                                                                  \
        }                                                                      \
    }

__global__ void __launch_bounds__(256, 2)
proj_mma(const float* __restrict__ bg) {
    __shared__ __half pAh[3][PLANE], pAl[3][PLANE], pBh[3][PLANE];
    int t = threadIdx.x, lane = t & 31, warp = t >> 5;
    int wm = warp >> 2, wn = warp & 3;
    int g = lane >> 2, c = lane & 3;
    int bn = blockIdx.x, bm = blockIdx.y;
    int nb = bn * 128;
    int abase = bm * 128;

    unsigned pAh_u = (unsigned)__cvta_generic_to_shared(pAh);
    unsigned pAl_u = (unsigned)__cvta_generic_to_shared(pAl);
    unsigned pBh_u = (unsigned)__cvta_generic_to_shared(pBh);
    int row = t >> 1, ch = (t & 1) * 8;
    int chsw = ch ^ ((row & 4) << 1);
    GEMM_LANEOFF()

    float acc[4][4][4];
    #pragma unroll
    for (int am = 0; am < 4; am++)
        #pragma unroll
        for (int an = 0; an < 4; an++)
            #pragma unroll
            for (int v = 0; v < 4; v++) acc[am][an][v] = 0.0f;

    PROJ_ISSUE(0, 0)
    PROJ_ISSUE(1, 1)
    for (int kt = 0; kt < 16; kt++) {
        if (kt < 15) cp_wait1(); else cp_wait0();
        __syncthreads();
        if (kt <= 13) {
            int nbuf = (kt + 2) % 3;
            PROJ_ISSUE(nbuf, kt + 2)
        }
        PROJ_KTILE(kt % 3)
    }

    #pragma unroll
    for (int am = 0; am < 4; am++) {
        int tok = abase + wm * 64 + am * 16 + g;
        int rr = tok >> 8, iw = tok & 255;
        #pragma unroll
        for (int an = 0; an < 4; an++) {
            int gc = nb + wn * 32 + an * 8 + 2 * c;
            float a0 = acc[am][an][0], a1 = acc[am][an][1];
            float a2 = acc[am][an][2], a3 = acc[am][an][3];
            if (gc < 256) {                       // q: fp32, [rh][i][d]
                int hh = gc >> 5, d8 = gc & 31;
                float* p0 = g_q + ((size_t)((rr * 8 + hh) * 256 + iw)) * 32 + d8;
                *(float2*)p0            = make_float2(a0, a1);
                *(float2*)(p0 + 8 * 32) = make_float2(a2, a3);
            } else if (gc < 512) {                // k: bf16 split, [rh][j][d]
                int cq = gc - 256;
                int hh = cq >> 5, d8 = cq & 31;
                size_t b0 = ((size_t)((rr * 8 + hh) * 256 + iw)) * 32 + d8;
                unsigned hi0, lo0, hi1, lo1;
                split2(a0, a1, hi0, lo0);
                split2(a2, a3, hi1, lo1);
                *(unsigned*)&g_kh[b0] = hi0;  *(unsigned*)&g_kl[b0] = lo0;
                *(unsigned*)&g_kh[b0 + 256] = hi1;  *(unsigned*)&g_kl[b0 + 256] = lo1;
            } else if (gc < 768) {                // v: bf16 split, transposed [rh][d][j]
                int cq = gc - 512;
                int hh = cq >> 5, d8 = cq & 31;
                size_t vb = ((size_t)((rr * 8 + hh) * 32 + d8)) * 256 + iw;
                __nv_bfloat16 h0, l0, h1, l1;
                split_bf16(a0, h0, l0);  g_vh[vb] = h0;        g_vl[vb] = l0;
                split_bf16(a1, h1, l1);  g_vh[vb + 256] = h1;  g_vl[vb + 256] = l1;
                split_bf16(a2, h0, l0);  g_vh[vb + 8] = h0;    g_vl[vb + 8] = l0;
                split_bf16(a3, h1, l1);  g_vh[vb + 264] = h1;  g_vl[vb + 264] = l1;
            } else {                              // gate: sigmoid fp32
                int gcol = gc - 768;
                float2 bg2 = *(const float2*)(bg + gcol);
                float* p0 = g_gate + (size_t)tok * 256 + gcol;
                float* p1 = p0 + 8 * 256;
                *(float2*)p0 = make_float2(1.0f / (1.0f + __expf(-(a0 + bg2.x))),
                                           1.0f / (1.0f + __expf(-(a1 + bg2.y))));
                *(float2*)p1 = make_float2(1.0f / (1.0f + __expf(-(a2 + bg2.x))),
                                           1.0f / (1.0f + __expf(-(a3 + bg2.y))));
            }
        }
    }
}

// ---------------- kernel 5: output projection (bf16x3, unchanged) ----------------
#define GEMM_ISSUE(buf, kt, Ahp, Alp, Bhp, Blp, abase, nbase)                  \
    {                                                                          \
        int k0 = (kt) * 16 + ch;                                               \
        unsigned doff = ((unsigned)(buf) * PLANE + row * RS + chsw) * 2;       \
        CP16(sAh_u + doff, (Ahp) + (size_t)((abase) + row) * 256 + k0);        \
        CP16(sAl_u + doff, (Alp) + (size_t)((abase) + row) * 256 + k0);        \
        CP16(sBh_u + doff, (Bhp) + (size_t)((nbase) + row) * 256 + k0);        \
        CP16(sBl_u + doff, (Blp) + (size_t)((nbase) + row) * 256 + k0);        \
        cp_commit();                                                           \
    }

#define GEMM_KTILE(st)                                                         \
    {                                                                          \
        unsigned stoff = (unsigned)(st) * PLANE * 2;                           \
        unsigned bh[4][2], bl[4][2];                                           \
        _Pragma("unroll")                                                      \
        for (int p = 0; p < 2; p++) {                                          \
            unsigned bo = ((wn * 32 + p * 16 + brow) * RS + bchnk) * 2;        \
            LDSM4(bh[2*p][0], bh[2*p][1], bh[2*p+1][0], bh[2*p+1][1],          \
                  sBh_u + stoff + bo)                                          \
            LDSM4(bl[2*p][0], bl[2*p][1], bl[2*p+1][0], bl[2*p+1][1],          \
                  sBl_u + stoff + bo)                                          \
        }                                                                      \
        _Pragma("unroll")                                                      \
        for (int am = 0; am < 4; am++) {                                       \
            unsigned ao = ((wm * 64 + am * 16 + arow) * RS + achnk) * 2;       \
            unsigned ah0, ah1, ah2, ah3, al0, al1, al2, al3;                   \
            LDSM4(ah0, ah1, ah2, ah3, sAh_u + stoff + ao)                      \
            LDSM4(al0, al1, al2, al3, sAl_u + stoff + ao)                      \
            _Pragma("unroll")                                                  \
            for (int an = 0; an < 4; an++) {                                   \
                float* ac = acc[am][an];                                       \
                mma_bf16(ac, ah0, ah1, ah2, ah3, bh[an][0], bh[an][1]);        \
                mma_bf16(ac, ah0, ah1, ah2, ah3, bl[an][0], bl[an][1]);        \
                mma_bf16(ac, al0, al1, al2, al3, bh[an][0], bh[an][1]);        \
            }                                                                  \
        }                                                                      \
    }

__global__ void __launch_bounds__(256, 2)
out_mma(const float* __restrict__ bo, float* __restrict__ out) {
    __shared__ __nv_bfloat16 sAh[3][PLANE], sAl[3][PLANE];
    __shared__ __nv_bfloat16 sBh[3][PLANE], sBl[3][PLANE];
    int t = threadIdx.x, lane = t & 31, warp = t >> 5;
    int wm = warp >> 2, wn = warp & 3;
    int g = lane >> 2, c = lane & 3;
    int bn = blockIdx.x, bm = blockIdx.y;
    int nb = bn * 128;
    int abase = bm * 128;

    unsigned sAh_u = (unsigned)__cvta_generic_to_shared(sAh);
    unsigned sAl_u = (unsigned)__cvta_generic_to_shared(sAl);
    unsigned sBh_u = (unsigned)__cvta_generic_to_shared(sBh);
    unsigned sBl_u = (unsigned)__cvta_generic_to_shared(sBl);
    int row = t >> 1, ch = (t & 1) * 8;
    int chsw = ch ^ ((row & 4) << 1);
    GEMM_LANEOFF()

    float acc[4][4][4];
    #pragma unroll
    for (int am = 0; am < 4; am++)
        #pragma unroll
        for (int an = 0; an < 4; an++)
            #pragma unroll
            for (int v = 0; v < 4; v++) acc[am][an][v] = 0.0f;

    GEMM_ISSUE(0, 0, g_atth, g_attl, g_woh, g_wol, abase, nb)
    GEMM_ISSUE(1, 1, g_atth, g_attl, g_woh, g_wol, abase, nb)
    for (int kt = 0; kt < 16; kt++) {
        if (kt < 15) cp_wait1(); else cp_wait0();
        __syncthreads();
        if (kt <= 13) {
            int nbuf = (kt + 2) % 3;
            GEMM_ISSUE(nbuf, kt + 2, g_atth, g_attl, g_woh, g_wol, abase, nb)
        }
        GEMM_KTILE(kt % 3)
    }

    #pragma unroll
    for (int am = 0; am < 4; am++) {
        int tok = abase + wm * 64 + am * 16 + g;
        #pragma unroll
        for (int an = 0; an < 4; an++) {
            int gc = nb + wn * 32 + an * 8 + 2 * c;
            float2 bo2 = *(const float2*)(bo + gc);
            float* p0 = out + (size_t)tok * 256 + gc;
            float* p1 = p0 + 8 * 256;
            *(float2*)p0 = make_float2(acc[am][an][0] + bo2.x, acc[am][an][1] + bo2.y);
            *(float2*)p1 = make_float2(acc[am][an][2] + bo2.x, acc[am][an][3] + bo2.y);
        }
    }
}

// ---------------- kernel 4: attention via bf16x3 mma.sync (16 warps, 16 q/warp) ----
// bias read from gmem with one-chunk register prefetch; KV staged via cp.async
#define A_K_OFF   0
#define A_KL_OFF  2560                // 32 rows * 80 B per plane
#define A_VH_OFF  5120
#define A_VL_OFF  7680
#define A_STAGE   10240
#define A_SMEM    (3 * A_STAGE)       // 30720

__global__ void __launch_bounds__(512, 1)
attn_mma(const unsigned int* __restrict__ mask) {
    extern __shared__ char asmem[];
    __shared__ unsigned mwords[8];

    int t = threadIdx.x, lane = t & 31, w = t >> 5;   // w = 0..15
    int g = lane >> 2, c = lane & 3;
    int rh = blockIdx.x;
    int r = rh >> 3, h = rh & 7;
    unsigned smem_u = (unsigned)__cvta_generic_to_shared(asmem);

    // key-mask ballot words
    if (w == 0) {
        #pragma unroll
        for (int q = 0; q < 8; q++) {
            unsigned bit = (mask[r * 256 + q * 32 + lane] != 0u) ? 1u : 0u;
            unsigned word = __ballot_sync(0xffffffffu, bit);
            if (lane == 0) mwords[q] = word;
        }
    }

    const float sc = 0.17677669529663689f;   // 32^-0.5
    int i0 = w * 16 + g, i1 = i0 + 8;
    int rowv0 = (mask[r * 256 + i0] != 0u);
    int rowv1 = (mask[r * 256 + i1] != 0u);

    // Q fragments (scaled, split)
    unsigned qh[2][4], ql[2][4];
    {
        const float* q0 = g_q + ((size_t)rh * 256 + i0) * 32;
        const float* q1 = g_q + ((size_t)rh * 256 + i1) * 32;
        #pragma unroll
        for (int ks = 0; ks < 2; ks++) {
            float2 x0 = *(const float2*)(q0 + ks * 16 + 2 * c);
            float2 x1 = *(const float2*)(q1 + ks * 16 + 2 * c);
            float2 x2 = *(const float2*)(q0 + ks * 16 + 2 * c + 8);
            float2 x3 = *(const float2*)(q1 + ks * 16 + 2 * c + 8);
            split2(x0.x * sc, x0.y * sc, qh[ks][0], ql[ks][0]);
            split2(x1.x * sc, x1.y * sc, qh[ks][1], ql[ks][1]);
            split2(x2.x * sc, x2.y * sc, qh[ks][2], ql[ks][2]);
            split2(x3.x * sc, x3.y * sc, qh[ks][3], ql[ks][3]);
        }
    }

    float O[4][4];
    float l0 = 0.0f, l1 = 0.0f;
    #pragma unroll
    for (int dt = 0; dt < 4; dt++)
        #pragma unroll
        for (int v = 0; v < 4; v++) O[dt][v] = 0.0f;

    // bias row pointers ([h][i][j] layout, half2 at even j)
    const __half2* bR0 = (const __half2*)&g_bias[((size_t)(h * 256 + i0)) * 256 + 2 * c];
    const __half2* bR1 = (const __half2*)&g_bias[((size_t)(h * 256 + i1)) * 256 + 2 * c];

    const __nv_bfloat16* khb = g_kh + (size_t)rh * 256 * 32;
    const __nv_bfloat16* klb = g_kl + (size_t)rh * 256 * 32;
    const __nv_bfloat16* vhb = g_vh + (size_t)rh * 32 * 256;
    const __nv_bfloat16* vlb = g_vl + (size_t)rh * 32 * 256;

    // per-chunk cp.async (512 threads): exactly 1 KV 16B chunk per thread
    int kvp  = t >> 7;                 // plane 0..3
    int kvr  = (t >> 2) & 31;          // row 0..31
    int kvs  = t & 3;                  // 16B chunk within 64B row

    #define AISSUE(chv)                                                            \
    {                                                                              \
        unsigned sb = smem_u + (unsigned)((chv) % 3) * A_STAGE;                    \
        unsigned kvo = sb + (unsigned)kvp * 2560 + kvr * 80 + kvs * 16;            \
        if (kvp == 0)                                                              \
            CP16(kvo, khb + (size_t)((chv) * 32 + kvr) * 32 + kvs * 8);            \
        else if (kvp == 1)                                                         \
            CP16(kvo, klb + (size_t)((chv) * 32 + kvr) * 32 + kvs * 8);            \
        else if (kvp == 2)                                                         \
            CP16(kvo, vhb + (size_t)kvr * 256 + (chv) * 32 + kvs * 8);             \
        else                                                                       \
            CP16(kvo, vlb + (size_t)kvr * 256 + (chv) * 32 + kvs * 8);             \
        cp_commit();                                                               \
    }

    AISSUE(0)
    AISSUE(1)

    // prefetch bias registers for chunk 0
    __half2 bv0[4], bv1[4];
    #pragma unroll
    for (int jt = 0; jt < 4; jt++) {
        bv0[jt] = bR0[jt * 4];
        bv1[jt] = bR1[jt * 4];
    }

    int brow = (lane & 7) + ((lane >> 4) & 1) * 8;
    int bch  = ((lane >> 3) & 1) * 8;

    for (int chk = 0; chk < 8; chk++) {
        if (chk < 7) cp_wait1(); else cp_wait0();
        __syncthreads();
        if (chk + 2 < 8) AISSUE(chk + 2)

        // consume prefetched bias; immediately prefetch next chunk's bias
        __half2 cb0[4], cb1[4];
        #pragma unroll
        for (int jt = 0; jt < 4; jt++) { cb0[jt] = bv0[jt]; cb1[jt] = bv1[jt]; }
        if (chk < 7) {
            #pragma unroll
            for (int jt = 0; jt < 4; jt++) {
                bv0[jt] = bR0[(chk + 1) * 16 + jt * 4];
                bv1[jt] = bR1[(chk + 1) * 16 + jt * 4];
            }
        }

        int st = chk % 3;
        unsigned sb = smem_u + (unsigned)st * A_STAGE;

        // K fragments
        unsigned kfh[2][4][2], kfl[2][4][2];
        #pragma unroll
        for (int p = 0; p < 2; p++) {
            #pragma unroll
            for (int ks = 0; ks < 2; ks++) {
                unsigned ao = sb + A_K_OFF + (p * 16 + brow) * 80 + (ks * 16 + bch) * 2;
                LDSM4(kfh[ks][2*p][0], kfh[ks][2*p][1], kfh[ks][2*p+1][0], kfh[ks][2*p+1][1], ao)
                unsigned al_ = sb + A_KL_OFF + (p * 16 + brow) * 80 + (ks * 16 + bch) * 2;
                LDSM4(kfl[ks][2*p][0], kfl[ks][2*p][1], kfl[ks][2*p+1][0], kfl[ks][2*p+1][1], al_)
            }
        }

        // S = (q*sc) @ K^T  (bf16x3)
        float S[4][4];
        #pragma unroll
        for (int jt = 0; jt < 4; jt++) {
            #pragma unroll
            for (int v = 0; v < 4; v++) S[jt][v] = 0.0f;
            #pragma unroll
            for (int ks = 0; ks < 2; ks++) {
                mma_bf16(S[jt], qh[ks][0], qh[ks][1], qh[ks][2], qh[ks][3],
                         kfh[ks][jt][0], kfh[ks][jt][1]);
                mma_bf16(S[jt], qh[ks][0], qh[ks][1], qh[ks][2], qh[ks][3],
                         kfl[ks][jt][0], kfl[ks][jt][1]);
                mma_bf16(S[jt], ql[ks][0], ql[ks][1], ql[ks][2], ql[ks][3],
                         kfh[ks][jt][0], kfh[ks][jt][1]);
            }
        }

        // bias + mask + exp
        unsigned mb = mwords[chk];
        #pragma unroll
        for (int jt = 0; jt < 4; jt++) {
            int j0 = jt * 8 + 2 * c;
            float2 f0 = __half22float2(cb0[jt]);
            float2 f1 = __half22float2(cb1[jt]);
            unsigned jm0 = (mb >> j0) & 1u, jm1 = (mb >> (j0 + 1)) & 1u;
            float p00 = jm0 ? __expf(S[jt][0] + f0.x) : 0.0f;
            float p01 = jm1 ? __expf(S[jt][1] + f0.y) : 0.0f;
            float p10 = jm0 ? __expf(S[jt][2] + f1.x) : 0.0f;
            float p11 = jm1 ? __expf(S[jt][3] + f1.y) : 0.0f;
            if (!rowv0) { p00 = 1.0f; p01 = 1.0f; }
            if (!rowv1) { p10 = 1.0f; p11 = 1.0f; }
            l0 += p00 + p01;
            l1 += p10 + p11;
            S[jt][0] = p00; S[jt][1] = p01;
            S[jt][2] = p10; S[jt][3] = p11;
        }

        // O += P @ V  (P split exactly; V split)
        #pragma unroll
        for (int ks = 0; ks < 2; ks++) {
            unsigned vfh[4][2], vfl[4][2];
            #pragma unroll
            for (int p = 0; p < 2; p++) {
                unsigned ao = sb + A_VH_OFF + (p * 16 + brow) * 80 + (ks * 16 + bch) * 2;
                LDSM4(vfh[2*p][0], vfh[2*p][1], vfh[2*p+1][0], vfh[2*p+1][1], ao)
                unsigned al_ = sb + A_VL_OFF + (p * 16 + brow) * 80 + (ks * 16 + bch) * 2;
                LDSM4(vfl[2*p][0], vfl[2*p][1], vfl[2*p+1][0], vfl[2*p+1][1], al_)
            }
            const float* PA = S[2 * ks];
            const float* PB = S[2 * ks + 1];
            unsigned ah0, ah1, ah2, ah3, al0, al1, al2, al3;
            split2(PA[0], PA[1], ah0, al0);
            split2(PA[2], PA[3], ah1, al1);
            split2(PB[0], PB[1], ah2, al2);
            split2(PB[2], PB[3], ah3, al3);
            #pragma unroll
            for (int dt = 0; dt < 4; dt++) {
                mma_bf16(O[dt], ah0, ah1, ah2, ah3, vfh[dt][0], vfh[dt][1]);
                mma_bf16(O[dt], ah0, ah1, ah2, ah3, vfl[dt][0], vfl[dt][1]);
                mma_bf16(O[dt], al0, al1, al2, al3, vfh[dt][0], vfh[dt][1]);
            }
        }
    }
    #undef AISSUE

    // finalize: reduce l over quad, normalize, gate, split-store
    l0 += __shfl_xor_sync(0xffffffffu, l0, 1);
    l0 += __shfl_xor_sync(0xffffffffu, l0, 2);
    l1 += __shfl_xor_sync(0xffffffffu, l1, 1);
    l1 += __shfl_xor_sync(0xffffffffu, l1, 2);
    float inv0 = 1.0f / l0;
    float inv1 = 1.0f / l1;

    int tok0 = r * 256 + i0;
    int tok1 = r * 256 + i1;
    #pragma unroll
    for (int dt = 0; dt < 4; dt++) {
        int col = h * 32 + dt * 8 + 2 * c;
        float2 g0 = *(const float2*)&g_gate[(size_t)tok0 * 256 + col];
        float2 g1 = *(const float2*)&g_gate[(size_t)tok1 * 256 + col];
        float o00 = O[dt][0] * inv0 * g0.x;
        float o01 = O[dt][1] * inv0 * g0.y;
        float o10 = O[dt][2] * inv1 * g1.x;
        float o11 = O[dt][3] * inv1 * g1.y;
        unsigned hi0, lo0, hi1, lo1;
        split2(o00, o01, hi0, lo0);
        split2(o10, o11, hi1, lo1);
        *(unsigned*)&g_atth[(size_t)tok0 * 256 + col] = hi0;
        *(unsigned*)&g_attl[(size_t)tok0 * 256 + col] = lo0;
        *(unsigned*)&g_atth[(size_t)tok1 * 256 + col] = hi1;
        *(unsigned*)&g_attl[(size_t)tok1 * 256 + col] = lo1;
    }
}

// ---------------- launch ----------------
extern "C" void kernel_launch(void* const* d_in, const int* in_sizes, int n_in,
                              void* d_out, int out_size) {
    const float* x      = (const float*)d_in[0];
    const float* edges  = (const float*)d_in[1];
    const unsigned int* mask      = (const unsigned int*)d_in[2];
    const unsigned int* edge_mask = (const unsigned int*)d_in[3];
    const float* ln_g   = (const float*)d_in[4];
    const float* ln_b   = (const float*)d_in[5];
    const float* lne_g  = (const float*)d_in[6];
    const float* lne_b  = (const float*)d_in[7];
    const float* W_edge = (const float*)d_in[8];
    const float* Wq     = (const float*)d_in[9];
    const float* Wkv    = (const float*)d_in[10];
    const float* Wg     = (const float*)d_in[11];
    const float* bg     = (const float*)d_in[12];
    const float* Wo     = (const float*)d_in[13];
    const float* bo     = (const float*)d_in[14];
    float* out = (float*)d_out;

    cudaFuncSetAttribute(attn_mma, cudaFuncAttributeMaxDynamicSharedMemorySize, A_SMEM);

    prep_kernel<<<PREP_LN_BLKS + PREP_W_BLKS + PREP_BIAS_BLKS, 256>>>(
        x, ln_g, ln_b, Wq, Wkv, Wg, Wo, edges, lne_g, lne_b, W_edge, edge_mask);
    proj_mma<<<dim3(8, NTOK / 128), 256>>>(bg);
    attn_mma<<<R_DIM * H_N, 512, A_SMEM>>>(mask);
    out_mma<<<dim3(2, NTOK / 128), 256>>>(bo, out);
}